// round 5
// baseline (speedup 1.0000x reference)
#include <cuda_runtime.h>
#include <cuda_bf16.h>
#include <cstdint>

#define T_SEQ 2048
#define NB 2
#define DIM 1024
#define NH 16
#define HS 64
#define NT_ROWS 4096
#define NEG_INF_F (-1e9f)
#define NELEM (NT_ROWS * DIM)

// ---------------- scratch (__device__ globals: allocation-free rule) --------
__device__ __nv_bfloat16 g_Xqh[NELEM], g_Xql[NELEM];
__device__ __nv_bfloat16 g_Xrh[NELEM], g_Xrl[NELEM];
__device__ __nv_bfloat16 g_Wqh[DIM * DIM], g_Wql[DIM * DIM];
__device__ __nv_bfloat16 g_Wkh[DIM * DIM], g_Wkl[DIM * DIM];
__device__ __nv_bfloat16 g_Wvh[DIM * DIM], g_Wvl[DIM * DIM];
__device__ __nv_bfloat16 g_Woh[DIM * DIM], g_Wol[DIM * DIM];
__device__ __nv_bfloat16 g_Qh[NELEM], g_Ql[NELEM];
__device__ __nv_bfloat16 g_Kh[NELEM], g_Kl[NELEM];
__device__ __nv_bfloat16 g_Vh[NELEM], g_Vl[NELEM];
__device__ __nv_bfloat16 g_Vth[NELEM], g_Vtl[NELEM];
__device__ __nv_bfloat16 g_Oh[NELEM], g_Ol[NELEM];

// ---------------- helpers ---------------------------------------------------
__device__ __forceinline__ void split2(float x, __nv_bfloat16& h, __nv_bfloat16& l) {
    h = __float2bfloat16(x);
    l = __float2bfloat16(x - __bfloat162float(h));
}
__device__ __forceinline__ unsigned pk(__nv_bfloat16 a, __nv_bfloat16 b) {
    return (unsigned)__bfloat16_as_ushort(a) | ((unsigned)__bfloat16_as_ushort(b) << 16);
}
__device__ __forceinline__ void split_pack2(float x0, float x1, unsigned& ph, unsigned& pl) {
    __nv_bfloat16 h0, l0, h1, l1;
    split2(x0, h0, l0);
    split2(x1, h1, l1);
    ph = pk(h0, h1);
    pl = pk(l0, l1);
}
__device__ __forceinline__ void mma16816(float (&d)[4], const unsigned (&a)[4],
                                         unsigned b0, unsigned b1) {
    asm volatile(
        "mma.sync.aligned.m16n8k16.row.col.f32.bf16.bf16.f32 "
        "{%0,%1,%2,%3}, {%4,%5,%6,%7}, {%8,%9}, {%0,%1,%2,%3};"
        : "+f"(d[0]), "+f"(d[1]), "+f"(d[2]), "+f"(d[3])
        : "r"(a[0]), "r"(a[1]), "r"(a[2]), "r"(a[3]), "r"(b0), "r"(b1));
}
__device__ __forceinline__ uint32_t smem_u32(const void* p) {
    uint32_t a;
    asm("{ .reg .u64 t; cvta.to.shared.u64 t, %1; cvt.u32.u64 %0, t; }" : "=r"(a) : "l"(p));
    return a;
}
__device__ __forceinline__ void cp16(void* smem_dst, const void* gsrc) {
    uint32_t s = smem_u32(smem_dst);
    asm volatile("cp.async.cg.shared.global [%0], [%1], 16;" :: "r"(s), "l"(gsrc) : "memory");
}
#define CP_COMMIT() asm volatile("cp.async.commit_group;" ::: "memory")
#define CP_WAIT1() asm volatile("cp.async.wait_group 1;" ::: "memory")

// ---------------- split kernels ---------------------------------------------
__global__ __launch_bounds__(256) void split_x(const float* __restrict__ X,
                                               __nv_bfloat16* __restrict__ Xh,
                                               __nv_bfloat16* __restrict__ Xl) {
    size_t i = ((size_t)blockIdx.x * 256 + threadIdx.x) * 4;
    float4 v = *(const float4*)(X + i);
    __nv_bfloat16 h0, l0, h1, l1, h2, l2, h3, l3;
    split2(v.x, h0, l0); split2(v.y, h1, l1);
    split2(v.z, h2, l2); split2(v.w, h3, l3);
    *(unsigned*)&Xh[i]     = pk(h0, h1);
    *(unsigned*)&Xh[i + 2] = pk(h2, h3);
    *(unsigned*)&Xl[i]     = pk(l0, l1);
    *(unsigned*)&Xl[i + 2] = pk(l2, l3);
}

__global__ __launch_bounds__(256) void split_wT(const float* __restrict__ W,
                                                __nv_bfloat16* __restrict__ Wth,
                                                __nv_bfloat16* __restrict__ Wtl) {
    __shared__ float S[32][33];
    const int n0 = blockIdx.x * 32, k0 = blockIdx.y * 32;
    const int tid = threadIdx.x;
#pragma unroll
    for (int i = tid; i < 1024; i += 256) {
        int r = i >> 5, c = i & 31;
        S[r][c] = W[(size_t)(k0 + r) * DIM + n0 + c];
    }
    __syncthreads();
#pragma unroll
    for (int i = tid; i < 1024; i += 256) {
        int rr = i >> 5, cc = i & 31;
        __nv_bfloat16 h, l;
        split2(S[cc][rr], h, l);
        Wth[(size_t)(n0 + rr) * DIM + k0 + cc] = h;
        Wtl[(size_t)(n0 + rr) * DIM + k0 + cc] = l;
    }
}

__global__ __launch_bounds__(256) void transpose_v(const __nv_bfloat16* __restrict__ Vh,
                                                   const __nv_bfloat16* __restrict__ Vl,
                                                   __nv_bfloat16* __restrict__ Vth,
                                                   __nv_bfloat16* __restrict__ Vtl) {
    __shared__ __nv_bfloat16 Sh[64][66], Sl[64][66];
    const int tt = blockIdx.x, bh = blockIdx.y;
    const int b = bh >> 4, h = bh & 15;
    const int tid = threadIdx.x;
#pragma unroll
    for (int i = tid; i < 64 * 32; i += 256) {
        int r = i >> 5, c2 = (i & 31) * 2;
        size_t g = (size_t)(b * T_SEQ + tt * 64 + r) * DIM + h * HS + c2;
        *(unsigned*)&Sh[r][c2] = *(const unsigned*)&Vh[g];
        *(unsigned*)&Sl[r][c2] = *(const unsigned*)&Vl[g];
    }
    __syncthreads();
#pragma unroll
    for (int i = tid; i < 64 * 32; i += 256) {
        int s = i >> 5, t2 = (i & 31) * 2;
        size_t g = (size_t)(bh * HS + s) * T_SEQ + tt * 64 + t2;
        *(unsigned*)&Vth[g] = pk(Sh[t2][s], Sh[t2 + 1][s]);
        *(unsigned*)&Vtl[g] = pk(Sl[t2][s], Sl[t2 + 1][s]);
    }
}

// ---------------- split-bf16 MMA GEMM, cp.async DB, term-major ---------------
#define GP 40
#define GEMM_NKT 32
#define GEMM_SMEM (8 * 128 * GP * 2)   // 81920 B

__global__ __launch_bounds__(256) void gemm_mma(
    const __nv_bfloat16* __restrict__ Ah_, const __nv_bfloat16* __restrict__ Al_,
    const __nv_bfloat16* __restrict__ Bh_, const __nv_bfloat16* __restrict__ Bl_,
    float* __restrict__ Cf, __nv_bfloat16* __restrict__ Ch,
    __nv_bfloat16* __restrict__ Cl, int mode, float scale) {
    extern __shared__ __nv_bfloat16 gsm[];
    const int tid = threadIdx.x;
    const int lane = tid & 31, wid = tid >> 5;
    const int gid = lane >> 2, tig = lane & 3;
    const int wm = (wid & 3) * 32, wn = (wid >> 2) * 64;
    const int bm = blockIdx.y * 128, bn = blockIdx.x * 128;

    const __nv_bfloat16* srcs[4] = {Ah_, Al_, Bh_, Bl_};

    auto load_stage = [&](int stage, int kt) {
        const int k0 = kt * 32;
        __nv_bfloat16* sb = gsm + stage * 4 * 128 * GP;
#pragma unroll
        for (int i = tid; i < 2048; i += 256) {
            int a = i >> 9, r = (i >> 2) & 127, c = i & 3;
            const int rbase = (a < 2) ? bm : bn;
            cp16(sb + a * 128 * GP + r * GP + c * 8,
                 srcs[a] + (size_t)(rbase + r) * DIM + k0 + c * 8);
        }
    };

    float acc[2][8][4];
#pragma unroll
    for (int mt = 0; mt < 2; mt++)
#pragma unroll
        for (int jn = 0; jn < 8; jn++)
#pragma unroll
            for (int e = 0; e < 4; e++) acc[mt][jn][e] = 0.f;

    load_stage(0, 0); CP_COMMIT();
    load_stage(1, 1); CP_COMMIT();

    for (int kt = 0; kt < GEMM_NKT; kt++) {
        const int cur = kt & 1;
        CP_WAIT1();
        __syncthreads();
        const __nv_bfloat16* As_h = gsm + (cur * 4 + 0) * 128 * GP;
        const __nv_bfloat16* As_l = gsm + (cur * 4 + 1) * 128 * GP;
        const __nv_bfloat16* Bs_h = gsm + (cur * 4 + 2) * 128 * GP;
        const __nv_bfloat16* Bs_l = gsm + (cur * 4 + 3) * 128 * GP;
#pragma unroll
        for (int kk = 0; kk < 2; kk++) {
            const int kc = kk * 16 + 2 * tig;
            unsigned ah[2][4], al[2][4];
#pragma unroll
            for (int mt = 0; mt < 2; mt++) {
                int row = wm + 16 * mt + gid;
                ah[mt][0] = *(const unsigned*)&As_h[row * GP + kc];
                ah[mt][1] = *(const unsigned*)&As_h[(row + 8) * GP + kc];
                ah[mt][2] = *(const unsigned*)&As_h[row * GP + kc + 8];
                ah[mt][3] = *(const unsigned*)&As_h[(row + 8) * GP + kc + 8];
                al[mt][0] = *(const unsigned*)&As_l[row * GP + kc];
                al[mt][1] = *(const unsigned*)&As_l[(row + 8) * GP + kc];
                al[mt][2] = *(const unsigned*)&As_l[row * GP + kc + 8];
                al[mt][3] = *(const unsigned*)&As_l[(row + 8) * GP + kc + 8];
            }
            // half-groups of 4 n-tiles; within a group: term-major ordering so
            // same-accumulator MMAs are 8 apart (breaks RAW chains).
#pragma unroll
            for (int half = 0; half < 2; half++) {
                unsigned bh[4][2], bl[4][2];
#pragma unroll
                for (int j = 0; j < 4; j++) {
                    int n = wn + 8 * (half * 4 + j) + gid;
                    bh[j][0] = *(const unsigned*)&Bs_h[n * GP + kc];
                    bh[j][1] = *(const unsigned*)&Bs_h[n * GP + kc + 8];
                    bl[j][0] = *(const unsigned*)&Bs_l[n * GP + kc];
                    bl[j][1] = *(const unsigned*)&Bs_l[n * GP + kc + 8];
                }
#pragma unroll
                for (int j = 0; j < 4; j++)
#pragma unroll
                    for (int mt = 0; mt < 2; mt++)
                        mma16816(acc[mt][half * 4 + j], ah[mt], bh[j][0], bh[j][1]);
#pragma unroll
                for (int j = 0; j < 4; j++)
#pragma unroll
                    for (int mt = 0; mt < 2; mt++)
                        mma16816(acc[mt][half * 4 + j], ah[mt], bl[j][0], bl[j][1]);
#pragma unroll
                for (int j = 0; j < 4; j++)
#pragma unroll
                    for (int mt = 0; mt < 2; mt++)
                        mma16816(acc[mt][half * 4 + j], al[mt], bh[j][0], bh[j][1]);
            }
        }
        __syncthreads();
        if (kt + 2 < GEMM_NKT) load_stage(cur, kt + 2);
        CP_COMMIT();
    }

#pragma unroll
    for (int mt = 0; mt < 2; mt++) {
        int row0 = bm + wm + 16 * mt + gid;
#pragma unroll
        for (int jn = 0; jn < 8; jn++) {
            int col = bn + wn + 8 * jn + 2 * tig;
            float x0 = acc[mt][jn][0] * scale, x1 = acc[mt][jn][1] * scale;
            float x2 = acc[mt][jn][2] * scale, x3 = acc[mt][jn][3] * scale;
            if (mode == 0) {
                *(float2*)&Cf[(size_t)row0 * DIM + col] = make_float2(x0, x1);
                *(float2*)&Cf[(size_t)(row0 + 8) * DIM + col] = make_float2(x2, x3);
            } else {
                unsigned ph, pl;
                split_pack2(x0, x1, ph, pl);
                *(unsigned*)&Ch[(size_t)row0 * DIM + col] = ph;
                *(unsigned*)&Cl[(size_t)row0 * DIM + col] = pl;
                split_pack2(x2, x3, ph, pl);
                *(unsigned*)&Ch[(size_t)(row0 + 8) * DIM + col] = ph;
                *(unsigned*)&Cl[(size_t)(row0 + 8) * DIM + col] = pl;
            }
        }
    }
}

// ---------------- flash attention: MMA + cp.async KV, term-major -------------
#define AP 72
#define ATTN_NKT (T_SEQ / 64)
#define ATTN_SMEM ((2 * 128 + 8 * 64) * AP * 2)   // 110592 B

__global__ __launch_bounds__(256) void attn_mma(
    const __nv_bfloat16* __restrict__ Qh_, const __nv_bfloat16* __restrict__ Ql_,
    const __nv_bfloat16* __restrict__ Kh_, const __nv_bfloat16* __restrict__ Kl_,
    const __nv_bfloat16* __restrict__ Vth_, const __nv_bfloat16* __restrict__ Vtl_,
    const float* __restrict__ mask,
    __nv_bfloat16* __restrict__ Oh_, __nv_bfloat16* __restrict__ Ol_) {
    extern __shared__ __nv_bfloat16 asm_[];
    __nv_bfloat16* Qh = asm_;
    __nv_bfloat16* Ql = Qh + 128 * AP;
    __nv_bfloat16* KV = Ql + 128 * AP;

    const int tid = threadIdx.x;
    const int lane = tid & 31, wid = tid >> 5;
    const int gid = lane >> 2, tig = lane & 3;
    const int bq = blockIdx.x, h = blockIdx.y, b = blockIdx.z;
    const int bh = b * NH + h;
    const int qrow0 = b * T_SEQ + bq * 128;

    auto load_kv = [&](int stage, int kt) {
        const int krow0 = b * T_SEQ + kt * 64;
        __nv_bfloat16* sb = KV + stage * 4 * 64 * AP;
#pragma unroll
        for (int i = tid; i < 2048; i += 256) {
            int a = i >> 9, r = (i >> 3) & 63, c = i & 7;
            __nv_bfloat16* dst = sb + a * 64 * AP + r * AP + c * 8;
            if (a == 0)
                cp16(dst, Kh_ + (size_t)(krow0 + r) * DIM + h * HS + c * 8);
            else if (a == 1)
                cp16(dst, Kl_ + (size_t)(krow0 + r) * DIM + h * HS + c * 8);
            else if (a == 2)
                cp16(dst, Vth_ + (size_t)(bh * HS + r) * T_SEQ + kt * 64 + c * 8);
            else
                cp16(dst, Vtl_ + (size_t)(bh * HS + r) * T_SEQ + kt * 64 + c * 8);
        }
    };

#pragma unroll
    for (int i = tid; i < 128 * 8; i += 256) {
        int r = i >> 3, c8 = (i & 7) * 8;
        size_t g = (size_t)(qrow0 + r) * DIM + h * HS + c8;
        *(int4*)&Qh[r * AP + c8] = *(const int4*)&Qh_[g];
        *(int4*)&Ql[r * AP + c8] = *(const int4*)&Ql_[g];
    }

    load_kv(0, 0); CP_COMMIT();
    load_kv(1, 1); CP_COMMIT();

    float mi[2] = {-1e30f, -1e30f}, li[2] = {0.f, 0.f};
    float accO[8][4];
#pragma unroll
    for (int jn = 0; jn < 8; jn++)
#pragma unroll
        for (int e = 0; e < 4; e++) accO[jn][e] = 0.f;

    const int q0g = bq * 128 + 16 * wid + gid;
    const float* mrow = mask + (size_t)bh * T_SEQ * T_SEQ;
    __syncthreads();

    for (int kt = 0; kt < ATTN_NKT; kt++) {
        const int cur = kt & 1;
        CP_WAIT1();
        __syncthreads();
        const __nv_bfloat16* Kh_s = KV + (cur * 4 + 0) * 64 * AP;
        const __nv_bfloat16* Kl_s = KV + (cur * 4 + 1) * 64 * AP;
        const __nv_bfloat16* Vh_s = KV + (cur * 4 + 2) * 64 * AP;
        const __nv_bfloat16* Vl_s = KV + (cur * 4 + 3) * 64 * AP;

        // ---- mask prefetch (LDGs before the MMA block) ----
        float2 mr0[8], mr1[8];
#pragma unroll
        for (int jn = 0; jn < 8; jn++) {
            int c = kt * 64 + 8 * jn + 2 * tig;
            mr0[jn] = *(const float2*)&mrow[(size_t)q0g * T_SEQ + c];
            mr1[jn] = *(const float2*)&mrow[(size_t)(q0g + 8) * T_SEQ + c];
        }

        // ---- scores: S = Q @ K^T (term-major) ----
        float sc[8][4];
#pragma unroll
        for (int jn = 0; jn < 8; jn++)
#pragma unroll
            for (int e = 0; e < 4; e++) sc[jn][e] = 0.f;
#pragma unroll
        for (int kk = 0; kk < 4; kk++) {
            const int kc = kk * 16 + 2 * tig;
            const int row = 16 * wid + gid;
            unsigned qah[4], qal[4];
            qah[0] = *(const unsigned*)&Qh[row * AP + kc];
            qah[1] = *(const unsigned*)&Qh[(row + 8) * AP + kc];
            qah[2] = *(const unsigned*)&Qh[row * AP + kc + 8];
            qah[3] = *(const unsigned*)&Qh[(row + 8) * AP + kc + 8];
            qal[0] = *(const unsigned*)&Ql[row * AP + kc];
            qal[1] = *(const unsigned*)&Ql[(row + 8) * AP + kc];
            qal[2] = *(const unsigned*)&Ql[row * AP + kc + 8];
            qal[3] = *(const unsigned*)&Ql[(row + 8) * AP + kc + 8];
#pragma unroll
            for (int half = 0; half < 2; half++) {
                unsigned kfh[4][2], kfl[4][2];
#pragma unroll
                for (int j = 0; j < 4; j++) {
                    int n = 8 * (half * 4 + j) + gid;
                    kfh[j][0] = *(const unsigned*)&Kh_s[n * AP + kc];
                    kfh[j][1] = *(const unsigned*)&Kh_s[n * AP + kc + 8];
                    kfl[j][0] = *(const unsigned*)&Kl_s[n * AP + kc];
                    kfl[j][1] = *(const unsigned*)&Kl_s[n * AP + kc + 8];
                }
#pragma unroll
                for (int j = 0; j < 4; j++)
                    mma16816(sc[half * 4 + j], qah, kfh[j][0], kfh[j][1]);
#pragma unroll
                for (int j = 0; j < 4; j++)
                    mma16816(sc[half * 4 + j], qah, kfl[j][0], kfl[j][1]);
#pragma unroll
                for (int j = 0; j < 4; j++)
                    mma16816(sc[half * 4 + j], qal, kfh[j][0], kfh[j][1]);
            }
        }

        // ---- apply mask ----
#pragma unroll
        for (int jn = 0; jn < 8; jn++) {
            sc[jn][0] = fmaf(mr0[jn].x, NEG_INF_F, sc[jn][0]);
            sc[jn][1] = fmaf(mr0[jn].y, NEG_INF_F, sc[jn][1]);
            sc[jn][2] = fmaf(mr1[jn].x, NEG_INF_F, sc[jn][2]);
            sc[jn][3] = fmaf(mr1[jn].y, NEG_INF_F, sc[jn][3]);
        }

        // ---- online softmax ----
        float mx0 = -1e30f, mx1 = -1e30f;
#pragma unroll
        for (int jn = 0; jn < 8; jn++) {
            mx0 = fmaxf(mx0, fmaxf(sc[jn][0], sc[jn][1]));
            mx1 = fmaxf(mx1, fmaxf(sc[jn][2], sc[jn][3]));
        }
        mx0 = fmaxf(mx0, __shfl_xor_sync(0xffffffffu, mx0, 1));
        mx0 = fmaxf(mx0, __shfl_xor_sync(0xffffffffu, mx0, 2));
        mx1 = fmaxf(mx1, __shfl_xor_sync(0xffffffffu, mx1, 1));
        mx1 = fmaxf(mx1, __shfl_xor_sync(0xffffffffu, mx1, 2));
        float mn0 = fmaxf(mi[0], mx0), mn1 = fmaxf(mi[1], mx1);
        float corr0 = __expf(mi[0] - mn0), corr1 = __expf(mi[1] - mn1);
        mi[0] = mn0; mi[1] = mn1;
        float rs0 = 0.f, rs1 = 0.f;
#pragma unroll
        for (int jn = 0; jn < 8; jn++) {
            sc[jn][0] = __expf(sc[jn][0] - mn0); rs0 += sc[jn][0];
            sc[jn][1] = __expf(sc[jn][1] - mn0); rs0 += sc[jn][1];
            sc[jn][2] = __expf(sc[jn][2] - mn1); rs1 += sc[jn][2];
            sc[jn][3] = __expf(sc[jn][3] - mn1); rs1 += sc[jn][3];
        }
        rs0 += __shfl_xor_sync(0xffffffffu, rs0, 1);
        rs0 += __shfl_xor_sync(0xffffffffu, rs0, 2);
        rs1 += __shfl_xor_sync(0xffffffffu, rs1, 1);
        rs1 += __shfl_xor_sync(0xffffffffu, rs1, 2);
        li[0] = li[0] * corr0 + rs0;
        li[1] = li[1] * corr1 + rs1;
#pragma unroll
        for (int jn = 0; jn < 8; jn++) {
            accO[jn][0] *= corr0; accO[jn][1] *= corr0;
            accO[jn][2] *= corr1; accO[jn][3] *= corr1;
        }

        // ---- accO += P @ V (term-major) ----
#pragma unroll
        for (int kk2 = 0; kk2 < 4; kk2++) {
            const int j0 = 2 * kk2, j1 = 2 * kk2 + 1;
            unsigned pah[4], pal[4];
            split_pack2(sc[j0][0], sc[j0][1], pah[0], pal[0]);
            split_pack2(sc[j0][2], sc[j0][3], pah[1], pal[1]);
            split_pack2(sc[j1][0], sc[j1][1], pah[2], pal[2]);
            split_pack2(sc[j1][2], sc[j1][3], pah[3], pal[3]);
            const int kc = kk2 * 16 + 2 * tig;
#pragma unroll
            for (int half = 0; half < 2; half++) {
                unsigned vfh[4][2], vfl[4][2];
#pragma unroll
                for (int j = 0; j < 4; j++) {
                    int n = 8 * (half * 4 + j) + gid;
                    vfh[j][0] = *(const unsigned*)&Vh_s[n * AP + kc];
                    vfh[j][1] = *(const unsigned*)&Vh_s[n * AP + kc + 8];
                    vfl[j][0] = *(const unsigned*)&Vl_s[n * AP + kc];
                    vfl[j][1] = *(const unsigned*)&Vl_s[n * AP + kc + 8];
                }
#pragma unroll
                for (int j = 0; j < 4; j++)
                    mma16816(accO[half * 4 + j], pah, vfh[j][0], vfh[j][1]);
#pragma unroll
                for (int j = 0; j < 4; j++)
                    mma16816(accO[half * 4 + j], pah, vfl[j][0], vfl[j][1]);
#pragma unroll
                for (int j = 0; j < 4; j++)
                    mma16816(accO[half * 4 + j], pal, vfh[j][0], vfh[j][1]);
            }
        }
        __syncthreads();
        if (kt + 2 < ATTN_NKT) load_kv(cur, kt + 2);
        CP_COMMIT();
    }

    // ---- epilogue ----
    const float inv0 = 1.f / li[0], inv1 = 1.f / li[1];
    const int row0 = qrow0 + 16 * wid + gid;
#pragma unroll
    for (int jn = 0; jn < 8; jn++) {
        int col = h * HS + 8 * jn + 2 * tig;
        unsigned ph, pl;
        split_pack2(accO[jn][0] * inv0, accO[jn][1] * inv0, ph, pl);
        *(unsigned*)&Oh_[(size_t)row0 * DIM + col] = ph;
        *(unsigned*)&Ol_[(size_t)row0 * DIM + col] = pl;
        split_pack2(accO[jn][2] * inv1, accO[jn][3] * inv1, ph, pl);
        *(unsigned*)&Oh_[(size_t)(row0 + 8) * DIM + col] = ph;
        *(unsigned*)&Ol_[(size_t)(row0 + 8) * DIM + col] = pl;
    }
}

// ---------------------------------------------------------------------------
extern "C" void kernel_launch(void* const* d_in, const int* in_sizes, int n_in,
                              void* d_out, int out_size) {
    const float* Xq   = (const float*)d_in[0];
    const float* Xr   = (const float*)d_in[1];
    const float* mask = (const float*)d_in[2];
    const float* Wq   = (const float*)d_in[3];
    const float* Wk   = (const float*)d_in[4];
    const float* Wv   = (const float*)d_in[5];
    const float* Wo   = (const float*)d_in[6];
    float* out = (float*)d_out;

    __nv_bfloat16 *Xqh, *Xql, *Xrh, *Xrl;
    __nv_bfloat16 *Wqh, *Wql, *Wkh, *Wkl, *Wvh, *Wvl, *Woh, *Wol;
    __nv_bfloat16 *Qh, *Ql, *Kh, *Kl, *Vh, *Vl, *Vth, *Vtl, *Oh, *Ol;
    cudaGetSymbolAddress((void**)&Xqh, g_Xqh); cudaGetSymbolAddress((void**)&Xql, g_Xql);
    cudaGetSymbolAddress((void**)&Xrh, g_Xrh); cudaGetSymbolAddress((void**)&Xrl, g_Xrl);
    cudaGetSymbolAddress((void**)&Wqh, g_Wqh); cudaGetSymbolAddress((void**)&Wql, g_Wql);
    cudaGetSymbolAddress((void**)&Wkh, g_Wkh); cudaGetSymbolAddress((void**)&Wkl, g_Wkl);
    cudaGetSymbolAddress((void**)&Wvh, g_Wvh); cudaGetSymbolAddress((void**)&Wvl, g_Wvl);
    cudaGetSymbolAddress((void**)&Woh, g_Woh); cudaGetSymbolAddress((void**)&Wol, g_Wol);
    cudaGetSymbolAddress((void**)&Qh, g_Qh);   cudaGetSymbolAddress((void**)&Ql, g_Ql);
    cudaGetSymbolAddress((void**)&Kh, g_Kh);   cudaGetSymbolAddress((void**)&Kl, g_Kl);
    cudaGetSymbolAddress((void**)&Vh, g_Vh);   cudaGetSymbolAddress((void**)&Vl, g_Vl);
    cudaGetSymbolAddress((void**)&Vth, g_Vth); cudaGetSymbolAddress((void**)&Vtl, g_Vtl);
    cudaGetSymbolAddress((void**)&Oh, g_Oh);   cudaGetSymbolAddress((void**)&Ol, g_Ol);

    cudaFuncSetAttribute(attn_mma, cudaFuncAttributeMaxDynamicSharedMemorySize, ATTN_SMEM);
    cudaFuncSetAttribute(gemm_mma, cudaFuncAttributeMaxDynamicSharedMemorySize, GEMM_SMEM);

    split_x<<<NELEM / 1024, 256>>>(Xq, Xqh, Xql);
    split_x<<<NELEM / 1024, 256>>>(Xr, Xrh, Xrl);
    dim3 gw(32, 32);
    split_wT<<<gw, 256>>>(Wq, Wqh, Wql);
    split_wT<<<gw, 256>>>(Wk, Wkh, Wkl);
    split_wT<<<gw, 256>>>(Wv, Wvh, Wvl);
    split_wT<<<gw, 256>>>(Wo, Wol ? Woh : Woh, Wol);  // (kept simple below)

    dim3 gg(DIM / 128, NT_ROWS / 128);
    gemm_mma<<<gg, 256, GEMM_SMEM>>>(Xqh, Xql, Wqh, Wql, nullptr, Qh, Ql, 1, 0.125f);
    gemm_mma<<<gg, 256, GEMM_SMEM>>>(Xrh, Xrl, Wkh, Wkl, nullptr, Kh, Kl, 1, 1.0f);
    gemm_mma<<<gg, 256, GEMM_SMEM>>>(Xrh, Xrl, Wvh, Wvl, nullptr, Vh, Vl, 1, 1.0f);

    transpose_v<<<dim3(T_SEQ / 64, NB * NH), 256>>>(Vh, Vl, Vth, Vtl);

    attn_mma<<<dim3(T_SEQ / 128, NH, NB), 256, ATTN_SMEM>>>(
        Qh, Ql, Kh, Kl, Vth, Vtl, mask, Oh, Ol);

    gemm_mma<<<gg, 256, GEMM_SMEM>>>(Oh, Ol, Woh, Wol, out, nullptr, nullptr, 0, 1.0f);
}

// round 6
// speedup vs baseline: 1.1295x; 1.1295x over previous
#include <cuda_runtime.h>
#include <cuda_bf16.h>
#include <cuda_fp16.h>
#include <cstdint>

#define T_SEQ 2048
#define NB 2
#define DIM 1024
#define NH 16
#define HS 64
#define NT_ROWS 4096
#define NEG_INF_F (-1e9f)
#define NELEM (NT_ROWS * DIM)

// ---------------- scratch (__device__ globals: allocation-free rule) --------
__device__ __nv_bfloat16 g_Xqh[NELEM], g_Xql[NELEM];
__device__ __nv_bfloat16 g_Xrh[NELEM], g_Xrl[NELEM];
__device__ __nv_bfloat16 g_Wqh[DIM * DIM], g_Wql[DIM * DIM];
__device__ __nv_bfloat16 g_Wkh[DIM * DIM], g_Wkl[DIM * DIM];
__device__ __nv_bfloat16 g_Wvh[DIM * DIM], g_Wvl[DIM * DIM];
__device__ __nv_bfloat16 g_Woh[DIM * DIM], g_Wol[DIM * DIM];
__device__ __half g_Q16h[NELEM], g_Q16l[NELEM];   // Q as fp16 hi/lo pair
__device__ __half g_K16[NELEM];                   // K single fp16
__device__ __half g_V16[NELEM];                   // V single fp16
__device__ __half g_Vt16[NELEM];                  // V transposed, single fp16
__device__ __nv_bfloat16 g_Oh[NELEM], g_Ol[NELEM];

// ---------------- helpers ---------------------------------------------------
__device__ __forceinline__ void split2(float x, __nv_bfloat16& h, __nv_bfloat16& l) {
    h = __float2bfloat16(x);
    l = __float2bfloat16(x - __bfloat162float(h));
}
__device__ __forceinline__ unsigned pk(__nv_bfloat16 a, __nv_bfloat16 b) {
    return (unsigned)__bfloat16_as_ushort(a) | ((unsigned)__bfloat16_as_ushort(b) << 16);
}
__device__ __forceinline__ unsigned pkh(__half a, __half b) {
    return (unsigned)__half_as_ushort(a) | ((unsigned)__half_as_ushort(b) << 16);
}
__device__ __forceinline__ void split_pack2(float x0, float x1, unsigned& ph, unsigned& pl) {
    __nv_bfloat16 h0, l0, h1, l1;
    split2(x0, h0, l0);
    split2(x1, h1, l1);
    ph = pk(h0, h1);
    pl = pk(l0, l1);
}
__device__ __forceinline__ void split_pack2h(float x0, float x1, unsigned& ph, unsigned& pl) {
    __half h0 = __float2half_rn(x0), h1 = __float2half_rn(x1);
    __half l0 = __float2half_rn(x0 - __half2float(h0));
    __half l1 = __float2half_rn(x1 - __half2float(h1));
    ph = pkh(h0, h1);
    pl = pkh(l0, l1);
}
// bf16 MMA
__device__ __forceinline__ void mma16816(float (&d)[4], const unsigned (&a)[4],
                                         unsigned b0, unsigned b1) {
    asm volatile(
        "mma.sync.aligned.m16n8k16.row.col.f32.bf16.bf16.f32 "
        "{%0,%1,%2,%3}, {%4,%5,%6,%7}, {%8,%9}, {%0,%1,%2,%3};"
        : "+f"(d[0]), "+f"(d[1]), "+f"(d[2]), "+f"(d[3])
        : "r"(a[0]), "r"(a[1]), "r"(a[2]), "r"(a[3]), "r"(b0), "r"(b1));
}
// fp16 MMA (fp32 accumulate)
__device__ __forceinline__ void mma16816h(float (&d)[4], const unsigned (&a)[4],
                                          unsigned b0, unsigned b1) {
    asm volatile(
        "mma.sync.aligned.m16n8k16.row.col.f32.f16.f16.f32 "
        "{%0,%1,%2,%3}, {%4,%5,%6,%7}, {%8,%9}, {%0,%1,%2,%3};"
        : "+f"(d[0]), "+f"(d[1]), "+f"(d[2]), "+f"(d[3])
        : "r"(a[0]), "r"(a[1]), "r"(a[2]), "r"(a[3]), "r"(b0), "r"(b1));
}
__device__ __forceinline__ uint32_t smem_u32(const void* p) {
    uint32_t a;
    asm("{ .reg .u64 t; cvta.to.shared.u64 t, %1; cvt.u32.u64 %0, t; }" : "=r"(a) : "l"(p));
    return a;
}
__device__ __forceinline__ void cp16(void* smem_dst, const void* gsrc) {
    uint32_t s = smem_u32(smem_dst);
    asm volatile("cp.async.cg.shared.global [%0], [%1], 16;" :: "r"(s), "l"(gsrc) : "memory");
}
#define CP_COMMIT() asm volatile("cp.async.commit_group;" ::: "memory")
#define CP_WAIT1() asm volatile("cp.async.wait_group 1;" ::: "memory")

// ---------------- split kernels ---------------------------------------------
__global__ __launch_bounds__(256) void split_x(const float* __restrict__ X,
                                               __nv_bfloat16* __restrict__ Xh,
                                               __nv_bfloat16* __restrict__ Xl) {
    size_t i = ((size_t)blockIdx.x * 256 + threadIdx.x) * 4;
    float4 v = *(const float4*)(X + i);
    __nv_bfloat16 h0, l0, h1, l1, h2, l2, h3, l3;
    split2(v.x, h0, l0); split2(v.y, h1, l1);
    split2(v.z, h2, l2); split2(v.w, h3, l3);
    *(unsigned*)&Xh[i]     = pk(h0, h1);
    *(unsigned*)&Xh[i + 2] = pk(h2, h3);
    *(unsigned*)&Xl[i]     = pk(l0, l1);
    *(unsigned*)&Xl[i + 2] = pk(l2, l3);
}

__global__ __launch_bounds__(256) void split_wT(const float* __restrict__ W,
                                                __nv_bfloat16* __restrict__ Wth,
                                                __nv_bfloat16* __restrict__ Wtl) {
    __shared__ float S[32][33];
    const int n0 = blockIdx.x * 32, k0 = blockIdx.y * 32;
    const int tid = threadIdx.x;
#pragma unroll
    for (int i = tid; i < 1024; i += 256) {
        int r = i >> 5, c = i & 31;
        S[r][c] = W[(size_t)(k0 + r) * DIM + n0 + c];
    }
    __syncthreads();
#pragma unroll
    for (int i = tid; i < 1024; i += 256) {
        int rr = i >> 5, cc = i & 31;
        __nv_bfloat16 h, l;
        split2(S[cc][rr], h, l);
        Wth[(size_t)(n0 + rr) * DIM + k0 + cc] = h;
        Wtl[(size_t)(n0 + rr) * DIM + k0 + cc] = l;
    }
}

// V [token][dim] fp16 -> Vt [(b,h,s)][token] fp16
__global__ __launch_bounds__(256) void transpose_v(const __half* __restrict__ V,
                                                   __half* __restrict__ Vt) {
    __shared__ __half S[64][66];
    const int tt = blockIdx.x, bh = blockIdx.y;
    const int b = bh >> 4, h = bh & 15;
    const int tid = threadIdx.x;
#pragma unroll
    for (int i = tid; i < 64 * 32; i += 256) {
        int r = i >> 5, c2 = (i & 31) * 2;
        size_t g = (size_t)(b * T_SEQ + tt * 64 + r) * DIM + h * HS + c2;
        *(unsigned*)&S[r][c2] = *(const unsigned*)&V[g];
    }
    __syncthreads();
#pragma unroll
    for (int i = tid; i < 64 * 32; i += 256) {
        int s = i >> 5, t2 = (i & 31) * 2;
        size_t g = (size_t)(bh * HS + s) * T_SEQ + tt * 64 + t2;
        *(unsigned*)&Vt[g] = pkh(S[t2][s], S[t2 + 1][s]);
    }
}

// ---------------- split-bf16 MMA GEMM, cp.async DB (R4 ordering) -------------
// modes: 0 = fp32 out; 1 = bf16 hi/lo pair; 2 = single fp16; 3 = fp16 hi/lo pair
#define GP 40
#define GEMM_NKT 32
#define GEMM_SMEM (8 * 128 * GP * 2)   // 81920 B

__global__ __launch_bounds__(256) void gemm_mma(
    const __nv_bfloat16* __restrict__ Ah_, const __nv_bfloat16* __restrict__ Al_,
    const __nv_bfloat16* __restrict__ Bh_, const __nv_bfloat16* __restrict__ Bl_,
    float* __restrict__ Cf, __nv_bfloat16* __restrict__ Cbh,
    __nv_bfloat16* __restrict__ Cbl, __half* __restrict__ Chh,
    __half* __restrict__ Chl, int mode, float scale) {
    extern __shared__ __nv_bfloat16 gsm[];
    const int tid = threadIdx.x;
    const int lane = tid & 31, wid = tid >> 5;
    const int gid = lane >> 2, tig = lane & 3;
    const int wm = (wid & 3) * 32, wn = (wid >> 2) * 64;
    const int bm = blockIdx.y * 128, bn = blockIdx.x * 128;

    const __nv_bfloat16* srcs[4] = {Ah_, Al_, Bh_, Bl_};

    auto load_stage = [&](int stage, int kt) {
        const int k0 = kt * 32;
        __nv_bfloat16* sb = gsm + stage * 4 * 128 * GP;
#pragma unroll
        for (int i = tid; i < 2048; i += 256) {
            int a = i >> 9, r = (i >> 2) & 127, c = i & 3;
            const int rbase = (a < 2) ? bm : bn;
            cp16(sb + a * 128 * GP + r * GP + c * 8,
                 srcs[a] + (size_t)(rbase + r) * DIM + k0 + c * 8);
        }
    };

    float acc[2][8][4];
#pragma unroll
    for (int mt = 0; mt < 2; mt++)
#pragma unroll
        for (int jn = 0; jn < 8; jn++)
#pragma unroll
            for (int e = 0; e < 4; e++) acc[mt][jn][e] = 0.f;

    load_stage(0, 0); CP_COMMIT();
    load_stage(1, 1); CP_COMMIT();

    for (int kt = 0; kt < GEMM_NKT; kt++) {
        const int cur = kt & 1;
        CP_WAIT1();
        __syncthreads();
        const __nv_bfloat16* As_h = gsm + (cur * 4 + 0) * 128 * GP;
        const __nv_bfloat16* As_l = gsm + (cur * 4 + 1) * 128 * GP;
        const __nv_bfloat16* Bs_h = gsm + (cur * 4 + 2) * 128 * GP;
        const __nv_bfloat16* Bs_l = gsm + (cur * 4 + 3) * 128 * GP;
#pragma unroll
        for (int kk = 0; kk < 2; kk++) {
            const int kc = kk * 16 + 2 * tig;
            unsigned ah[2][4], al[2][4];
#pragma unroll
            for (int mt = 0; mt < 2; mt++) {
                int row = wm + 16 * mt + gid;
                ah[mt][0] = *(const unsigned*)&As_h[row * GP + kc];
                ah[mt][1] = *(const unsigned*)&As_h[(row + 8) * GP + kc];
                ah[mt][2] = *(const unsigned*)&As_h[row * GP + kc + 8];
                ah[mt][3] = *(const unsigned*)&As_h[(row + 8) * GP + kc + 8];
                al[mt][0] = *(const unsigned*)&As_l[row * GP + kc];
                al[mt][1] = *(const unsigned*)&As_l[(row + 8) * GP + kc];
                al[mt][2] = *(const unsigned*)&As_l[row * GP + kc + 8];
                al[mt][3] = *(const unsigned*)&As_l[(row + 8) * GP + kc + 8];
            }
#pragma unroll
            for (int jn = 0; jn < 8; jn++) {
                int n = wn + 8 * jn + gid;
                unsigned bh0 = *(const unsigned*)&Bs_h[n * GP + kc];
                unsigned bh1 = *(const unsigned*)&Bs_h[n * GP + kc + 8];
                unsigned bl0 = *(const unsigned*)&Bs_l[n * GP + kc];
                unsigned bl1 = *(const unsigned*)&Bs_l[n * GP + kc + 8];
#pragma unroll
                for (int mt = 0; mt < 2; mt++) {
                    mma16816(acc[mt][jn], ah[mt], bh0, bh1);
                    mma16816(acc[mt][jn], ah[mt], bl0, bl1);
                    mma16816(acc[mt][jn], al[mt], bh0, bh1);
                }
            }
        }
        __syncthreads();
        if (kt + 2 < GEMM_NKT) load_stage(cur, kt + 2);
        CP_COMMIT();
    }

#pragma unroll
    for (int mt = 0; mt < 2; mt++) {
        int row0 = bm + wm + 16 * mt + gid;
#pragma unroll
        for (int jn = 0; jn < 8; jn++) {
            int col = bn + wn + 8 * jn + 2 * tig;
            float x0 = acc[mt][jn][0] * scale, x1 = acc[mt][jn][1] * scale;
            float x2 = acc[mt][jn][2] * scale, x3 = acc[mt][jn][3] * scale;
            if (mode == 0) {
                *(float2*)&Cf[(size_t)row0 * DIM + col] = make_float2(x0, x1);
                *(float2*)&Cf[(size_t)(row0 + 8) * DIM + col] = make_float2(x2, x3);
            } else if (mode == 1) {
                unsigned ph, pl;
                split_pack2(x0, x1, ph, pl);
                *(unsigned*)&Cbh[(size_t)row0 * DIM + col] = ph;
                *(unsigned*)&Cbl[(size_t)row0 * DIM + col] = pl;
                split_pack2(x2, x3, ph, pl);
                *(unsigned*)&Cbh[(size_t)(row0 + 8) * DIM + col] = ph;
                *(unsigned*)&Cbl[(size_t)(row0 + 8) * DIM + col] = pl;
            } else if (mode == 2) {
                *(unsigned*)&Chh[(size_t)row0 * DIM + col] =
                    pkh(__float2half_rn(x0), __float2half_rn(x1));
                *(unsigned*)&Chh[(size_t)(row0 + 8) * DIM + col] =
                    pkh(__float2half_rn(x2), __float2half_rn(x3));
            } else {
                unsigned ph, pl;
                split_pack2h(x0, x1, ph, pl);
                *(unsigned*)&Chh[(size_t)row0 * DIM + col] = ph;
                *(unsigned*)&Chl[(size_t)row0 * DIM + col] = pl;
                split_pack2h(x2, x3, ph, pl);
                *(unsigned*)&Chh[(size_t)(row0 + 8) * DIM + col] = ph;
                *(unsigned*)&Chl[(size_t)(row0 + 8) * DIM + col] = pl;
            }
        }
    }
}

// ---------------- flash attention: fp16, 2-term QK / 2-term PV ---------------
// Q fp16 hi/lo pair (resident); K,V single fp16 (streamed, double-buffered).
#define AP 72
#define ATTN_NKT (T_SEQ / 64)
#define ATTN_SMEM ((2 * 128 + 2 * 2 * 64) * AP * 2)   // 73728 B

__global__ __launch_bounds__(256) void attn_mma(
    const __half* __restrict__ Qh_, const __half* __restrict__ Ql_,
    const __half* __restrict__ K_, const __half* __restrict__ Vt_,
    const float* __restrict__ mask,
    __nv_bfloat16* __restrict__ Oh_, __nv_bfloat16* __restrict__ Ol_) {
    extern __shared__ __half asm_[];
    __half* Qh = asm_;                 // [128][AP]
    __half* Ql = Qh + 128 * AP;
    __half* KV = Ql + 128 * AP;        // stage s: K [64*AP], V [64*AP]

    const int tid = threadIdx.x;
    const int lane = tid & 31, wid = tid >> 5;
    const int gid = lane >> 2, tig = lane & 3;
    const int bq = blockIdx.x, h = blockIdx.y, b = blockIdx.z;
    const int bh = b * NH + h;
    const int qrow0 = b * T_SEQ + bq * 128;

    auto load_kv = [&](int stage, int kt) {
        const int krow0 = b * T_SEQ + kt * 64;
        __half* sb = KV + stage * 2 * 64 * AP;
#pragma unroll
        for (int i = tid; i < 1024; i += 256) {
            int a = i >> 9, r = (i >> 3) & 63, c = i & 7;
            __half* dst = sb + a * 64 * AP + r * AP + c * 8;
            if (a == 0)
                cp16(dst, K_ + (size_t)(krow0 + r) * DIM + h * HS + c * 8);
            else
                cp16(dst, Vt_ + (size_t)(bh * HS + r) * T_SEQ + kt * 64 + c * 8);
        }
    };

#pragma unroll
    for (int i = tid; i < 128 * 8; i += 256) {
        int r = i >> 3, c8 = (i & 7) * 8;
        size_t g = (size_t)(qrow0 + r) * DIM + h * HS + c8;
        *(int4*)&Qh[r * AP + c8] = *(const int4*)&Qh_[g];
        *(int4*)&Ql[r * AP + c8] = *(const int4*)&Ql_[g];
    }

    load_kv(0, 0); CP_COMMIT();
    load_kv(1, 1); CP_COMMIT();

    float mi[2] = {-1e30f, -1e30f}, li[2] = {0.f, 0.f};
    float accO[8][4];
#pragma unroll
    for (int jn = 0; jn < 8; jn++)
#pragma unroll
        for (int e = 0; e < 4; e++) accO[jn][e] = 0.f;

    const int q0g = bq * 128 + 16 * wid + gid;
    const float* mrow = mask + (size_t)bh * T_SEQ * T_SEQ;
    __syncthreads();

    for (int kt = 0; kt < ATTN_NKT; kt++) {
        const int cur = kt & 1;
        CP_WAIT1();
        __syncthreads();
        const __half* K_s = KV + (cur * 2 + 0) * 64 * AP;
        const __half* V_s = KV + (cur * 2 + 1) * 64 * AP;

        // ---- mask prefetch (LDGs before the MMA block) ----
        float2 mr0[8], mr1[8];
#pragma unroll
        for (int jn = 0; jn < 8; jn++) {
            int c = kt * 64 + 8 * jn + 2 * tig;
            mr0[jn] = *(const float2*)&mrow[(size_t)q0g * T_SEQ + c];
            mr1[jn] = *(const float2*)&mrow[(size_t)(q0g + 8) * T_SEQ + c];
        }

        // ---- scores: S = (Qh + Ql) @ K^T, fp16 2-term ----
        float sc[8][4];
#pragma unroll
        for (int jn = 0; jn < 8; jn++)
#pragma unroll
            for (int e = 0; e < 4; e++) sc[jn][e] = 0.f;
#pragma unroll
        for (int kk = 0; kk < 4; kk++) {
            const int kc = kk * 16 + 2 * tig;
            const int row = 16 * wid + gid;
            unsigned qah[4], qal[4];
            qah[0] = *(const unsigned*)&Qh[row * AP + kc];
            qah[1] = *(const unsigned*)&Qh[(row + 8) * AP + kc];
            qah[2] = *(const unsigned*)&Qh[row * AP + kc + 8];
            qah[3] = *(const unsigned*)&Qh[(row + 8) * AP + kc + 8];
            qal[0] = *(const unsigned*)&Ql[row * AP + kc];
            qal[1] = *(const unsigned*)&Ql[(row + 8) * AP + kc];
            qal[2] = *(const unsigned*)&Ql[row * AP + kc + 8];
            qal[3] = *(const unsigned*)&Ql[(row + 8) * AP + kc + 8];
#pragma unroll
            for (int jn = 0; jn < 8; jn++) {
                int n = 8 * jn + gid;
                unsigned kf0 = *(const unsigned*)&K_s[n * AP + kc];
                unsigned kf1 = *(const unsigned*)&K_s[n * AP + kc + 8];
                mma16816h(sc[jn], qah, kf0, kf1);
                mma16816h(sc[jn], qal, kf0, kf1);
            }
        }

        // ---- apply mask ----
#pragma unroll
        for (int jn = 0; jn < 8; jn++) {
            sc[jn][0] = fmaf(mr0[jn].x, NEG_INF_F, sc[jn][0]);
            sc[jn][1] = fmaf(mr0[jn].y, NEG_INF_F, sc[jn][1]);
            sc[jn][2] = fmaf(mr1[jn].x, NEG_INF_F, sc[jn][2]);
            sc[jn][3] = fmaf(mr1[jn].y, NEG_INF_F, sc[jn][3]);
        }

        // ---- online softmax ----
        float mx0 = -1e30f, mx1 = -1e30f;
#pragma unroll
        for (int jn = 0; jn < 8; jn++) {
            mx0 = fmaxf(mx0, fmaxf(sc[jn][0], sc[jn][1]));
            mx1 = fmaxf(mx1, fmaxf(sc[jn][2], sc[jn][3]));
        }
        mx0 = fmaxf(mx0, __shfl_xor_sync(0xffffffffu, mx0, 1));
        mx0 = fmaxf(mx0, __shfl_xor_sync(0xffffffffu, mx0, 2));
        mx1 = fmaxf(mx1, __shfl_xor_sync(0xffffffffu, mx1, 1));
        mx1 = fmaxf(mx1, __shfl_xor_sync(0xffffffffu, mx1, 2));
        float mn0 = fmaxf(mi[0], mx0), mn1 = fmaxf(mi[1], mx1);
        float corr0 = __expf(mi[0] - mn0), corr1 = __expf(mi[1] - mn1);
        mi[0] = mn0; mi[1] = mn1;
        float rs0 = 0.f, rs1 = 0.f;
#pragma unroll
        for (int jn = 0; jn < 8; jn++) {
            sc[jn][0] = __expf(sc[jn][0] - mn0); rs0 += sc[jn][0];
            sc[jn][1] = __expf(sc[jn][1] - mn0); rs0 += sc[jn][1];
            sc[jn][2] = __expf(sc[jn][2] - mn1); rs1 += sc[jn][2];
            sc[jn][3] = __expf(sc[jn][3] - mn1); rs1 += sc[jn][3];
        }
        rs0 += __shfl_xor_sync(0xffffffffu, rs0, 1);
        rs0 += __shfl_xor_sync(0xffffffffu, rs0, 2);
        rs1 += __shfl_xor_sync(0xffffffffu, rs1, 1);
        rs1 += __shfl_xor_sync(0xffffffffu, rs1, 2);
        li[0] = li[0] * corr0 + rs0;
        li[1] = li[1] * corr1 + rs1;
#pragma unroll
        for (int jn = 0; jn < 8; jn++) {
            accO[jn][0] *= corr0; accO[jn][1] *= corr0;
            accO[jn][2] *= corr1; accO[jn][3] *= corr1;
        }

        // ---- accO += (Ph + Pl) @ V, fp16 2-term ----
#pragma unroll
        for (int kk2 = 0; kk2 < 4; kk2++) {
            const int j0 = 2 * kk2, j1 = 2 * kk2 + 1;
            unsigned pah[4], pal[4];
            split_pack2h(sc[j0][0], sc[j0][1], pah[0], pal[0]);
            split_pack2h(sc[j0][2], sc[j0][3], pah[1], pal[1]);
            split_pack2h(sc[j1][0], sc[j1][1], pah[2], pal[2]);
            split_pack2h(sc[j1][2], sc[j1][3], pah[3], pal[3]);
            const int kc = kk2 * 16 + 2 * tig;
#pragma unroll
            for (int jn = 0; jn < 8; jn++) {
                int n = 8 * jn + gid;
                unsigned vf0 = *(const unsigned*)&V_s[n * AP + kc];
                unsigned vf1 = *(const unsigned*)&V_s[n * AP + kc + 8];
                mma16816h(accO[jn], pah, vf0, vf1);
                mma16816h(accO[jn], pal, vf0, vf1);
            }
        }
        __syncthreads();
        if (kt + 2 < ATTN_NKT) load_kv(cur, kt + 2);
        CP_COMMIT();
    }

    // ---- epilogue: normalize, split to bf16 pair for out-projection ----
    const float inv0 = 1.f / li[0], inv1 = 1.f / li[1];
    const int row0 = qrow0 + 16 * wid + gid;
#pragma unroll
    for (int jn = 0; jn < 8; jn++) {
        int col = h * HS + 8 * jn + 2 * tig;
        unsigned ph, pl;
        split_pack2(accO[jn][0] * inv0, accO[jn][1] * inv0, ph, pl);
        *(unsigned*)&Oh_[(size_t)row0 * DIM + col] = ph;
        *(unsigned*)&Ol_[(size_t)row0 * DIM + col] = pl;
        split_pack2(accO[jn][2] * inv1, accO[jn][3] * inv1, ph, pl);
        *(unsigned*)&Oh_[(size_t)(row0 + 8) * DIM + col] = ph;
        *(unsigned*)&Ol_[(size_t)(row0 + 8) * DIM + col] = pl;
    }
}

// ---------------------------------------------------------------------------
extern "C" void kernel_launch(void* const* d_in, const int* in_sizes, int n_in,
                              void* d_out, int out_size) {
    const float* Xq   = (const float*)d_in[0];
    const float* Xr   = (const float*)d_in[1];
    const float* mask = (const float*)d_in[2];
    const float* Wq   = (const float*)d_in[3];
    const float* Wk   = (const float*)d_in[4];
    const float* Wv   = (const float*)d_in[5];
    const float* Wo   = (const float*)d_in[6];
    float* out = (float*)d_out;

    __nv_bfloat16 *Xqh, *Xql, *Xrh, *Xrl;
    __nv_bfloat16 *Wqh, *Wql, *Wkh, *Wkl, *Wvh, *Wvl, *Woh, *Wol;
    __nv_bfloat16 *Oh, *Ol;
    __half *Q16h, *Q16l, *K16, *V16, *Vt16;
    cudaGetSymbolAddress((void**)&Xqh, g_Xqh); cudaGetSymbolAddress((void**)&Xql, g_Xql);
    cudaGetSymbolAddress((void**)&Xrh, g_Xrh); cudaGetSymbolAddress((void**)&Xrl, g_Xrl);
    cudaGetSymbolAddress((void**)&Wqh, g_Wqh); cudaGetSymbolAddress((void**)&Wql, g_Wql);
    cudaGetSymbolAddress((void**)&Wkh, g_Wkh); cudaGetSymbolAddress((void**)&Wkl, g_Wkl);
    cudaGetSymbolAddress((void**)&Wvh, g_Wvh); cudaGetSymbolAddress((void**)&Wvl, g_Wvl);
    cudaGetSymbolAddress((void**)&Woh, g_Woh); cudaGetSymbolAddress((void**)&Wol, g_Wol);
    cudaGetSymbolAddress((void**)&Q16h, g_Q16h); cudaGetSymbolAddress((void**)&Q16l, g_Q16l);
    cudaGetSymbolAddress((void**)&K16, g_K16);   cudaGetSymbolAddress((void**)&V16, g_V16);
    cudaGetSymbolAddress((void**)&Vt16, g_Vt16);
    cudaGetSymbolAddress((void**)&Oh, g_Oh);     cudaGetSymbolAddress((void**)&Ol, g_Ol);

    cudaFuncSetAttribute(attn_mma, cudaFuncAttributeMaxDynamicSharedMemorySize, ATTN_SMEM);
    cudaFuncSetAttribute(gemm_mma, cudaFuncAttributeMaxDynamicSharedMemorySize, GEMM_SMEM);

    // 1) split inputs
    split_x<<<NELEM / 1024, 256>>>(Xq, Xqh, Xql);
    split_x<<<NELEM / 1024, 256>>>(Xr, Xrh, Xrl);
    dim3 gw(32, 32);
    split_wT<<<gw, 256>>>(Wq, Wqh, Wql);
    split_wT<<<gw, 256>>>(Wk, Wkh, Wkl);
    split_wT<<<gw, 256>>>(Wv, Wvh, Wvl);
    split_wT<<<gw, 256>>>(Wo, Woh, Wol);

    // 2) projections (3-term bf16), epilogues in attention-ready formats
    dim3 gg(DIM / 128, NT_ROWS / 128);
    gemm_mma<<<gg, 256, GEMM_SMEM>>>(Xqh, Xql, Wqh, Wql, nullptr, nullptr, nullptr,
                                     Q16h, Q16l, 3, 0.125f);   // Q: fp16 pair
    gemm_mma<<<gg, 256, GEMM_SMEM>>>(Xrh, Xrl, Wkh, Wkl, nullptr, nullptr, nullptr,
                                     K16, nullptr, 2, 1.0f);   // K: single fp16
    gemm_mma<<<gg, 256, GEMM_SMEM>>>(Xrh, Xrl, Wvh, Wvl, nullptr, nullptr, nullptr,
                                     V16, nullptr, 2, 1.0f);   // V: single fp16

    // 3) V transpose (single fp16)
    transpose_v<<<dim3(T_SEQ / 64, NB * NH), 256>>>(V16, Vt16);

    // 4) flash attention (fp16 2-term QK / PV)
    attn_mma<<<dim3(T_SEQ / 128, NH, NB), 256, ATTN_SMEM>>>(
        Q16h, Q16l, K16, Vt16, mask, Oh, Ol);

    // 5) output projection (3-term bf16) -> fp32 d_out
    gemm_mma<<<gg, 256, GEMM_SMEM>>>(Oh, Ol, Woh, Wol, out, nullptr, nullptr,
                                     nullptr, nullptr, 0, 1.0f);
}

// round 7
// speedup vs baseline: 1.5942x; 1.4115x over previous
#include <cuda_runtime.h>
#include <cuda_fp16.h>
#include <cstdint>

#define T_SEQ 2048
#define NB 2
#define DIM 1024
#define NH 16
#define HS 64
#define NT_ROWS 4096
#define NEG_INF_F (-1e9f)
#define NELEM (NT_ROWS * DIM)

// ---------------- scratch (__device__ globals: allocation-free rule) --------
__device__ __half g_Xqh[NELEM], g_Xql[NELEM];   // X fp16 hi/lo pairs
__device__ __half g_Xrh[NELEM], g_Xrl[NELEM];
__device__ __half g_WqT[DIM * DIM];             // W transposed, single fp16
__device__ __half g_WkT[DIM * DIM];
__device__ __half g_WvT[DIM * DIM];
__device__ __half g_WoT[DIM * DIM];
__device__ __half g_Q16[NELEM];                 // Q single fp16
__device__ __half g_K16[NELEM];
__device__ __half g_V16[NELEM];
__device__ __half g_Vt16[NELEM];
__device__ __half g_O16h[NELEM], g_O16l[NELEM]; // O fp16 hi/lo pair

// ---------------- helpers ---------------------------------------------------
__device__ __forceinline__ unsigned pkh(__half a, __half b) {
    return (unsigned)__half_as_ushort(a) | ((unsigned)__half_as_ushort(b) << 16);
}
__device__ __forceinline__ void split2h(float x, __half& h, __half& l) {
    h = __float2half_rn(x);
    l = __float2half_rn(x - __half2float(h));
}
__device__ __forceinline__ void split_pack2h(float x0, float x1, unsigned& ph, unsigned& pl) {
    __half h0, l0, h1, l1;
    split2h(x0, h0, l0);
    split2h(x1, h1, l1);
    ph = pkh(h0, h1);
    pl = pkh(l0, l1);
}
// fp16 MMA, fp32 accumulate
__device__ __forceinline__ void mma16816h(float (&d)[4], const unsigned (&a)[4],
                                          unsigned b0, unsigned b1) {
    asm volatile(
        "mma.sync.aligned.m16n8k16.row.col.f32.f16.f16.f32 "
        "{%0,%1,%2,%3}, {%4,%5,%6,%7}, {%8,%9}, {%0,%1,%2,%3};"
        : "+f"(d[0]), "+f"(d[1]), "+f"(d[2]), "+f"(d[3])
        : "r"(a[0]), "r"(a[1]), "r"(a[2]), "r"(a[3]), "r"(b0), "r"(b1));
}
__device__ __forceinline__ uint32_t smem_u32(const void* p) {
    uint32_t a;
    asm("{ .reg .u64 t; cvta.to.shared.u64 t, %1; cvt.u32.u64 %0, t; }" : "=r"(a) : "l"(p));
    return a;
}
__device__ __forceinline__ void cp16(void* smem_dst, const void* gsrc) {
    uint32_t s = smem_u32(smem_dst);
    asm volatile("cp.async.cg.shared.global [%0], [%1], 16;" :: "r"(s), "l"(gsrc) : "memory");
}
#define CP_COMMIT() asm volatile("cp.async.commit_group;" ::: "memory")
#define CP_WAIT1() asm volatile("cp.async.wait_group 1;" ::: "memory")

// ---------------- split kernels ---------------------------------------------
// X f32 -> fp16 hi/lo pair
__global__ __launch_bounds__(256) void split_x(const float* __restrict__ X,
                                               __half* __restrict__ Xh,
                                               __half* __restrict__ Xl) {
    size_t i = ((size_t)blockIdx.x * 256 + threadIdx.x) * 4;
    float4 v = *(const float4*)(X + i);
    unsigned ph0, pl0, ph1, pl1;
    split_pack2h(v.x, v.y, ph0, pl0);
    split_pack2h(v.z, v.w, ph1, pl1);
    *(unsigned*)&Xh[i]     = ph0;
    *(unsigned*)&Xh[i + 2] = ph1;
    *(unsigned*)&Xl[i]     = pl0;
    *(unsigned*)&Xl[i + 2] = pl1;
}

// W [k][n] f32 -> Wt [n][k] single fp16
__global__ __launch_bounds__(256) void split_wT(const float* __restrict__ W,
                                                __half* __restrict__ Wt) {
    __shared__ float S[32][33];
    const int n0 = blockIdx.x * 32, k0 = blockIdx.y * 32;
    const int tid = threadIdx.x;
#pragma unroll
    for (int i = tid; i < 1024; i += 256) {
        int r = i >> 5, c = i & 31;
        S[r][c] = W[(size_t)(k0 + r) * DIM + n0 + c];
    }
    __syncthreads();
#pragma unroll
    for (int i = tid; i < 1024; i += 256) {
        int rr = i >> 5, cc = i & 31;
        Wt[(size_t)(n0 + rr) * DIM + k0 + cc] = __float2half_rn(S[cc][rr]);
    }
}

// V [token][dim] fp16 -> Vt [(b,h,s)][token] fp16
__global__ __launch_bounds__(256) void transpose_v(const __half* __restrict__ V,
                                                   __half* __restrict__ Vt) {
    __shared__ __half S[64][66];
    const int tt = blockIdx.x, bh = blockIdx.y;
    const int b = bh >> 4, h = bh & 15;
    const int tid = threadIdx.x;
#pragma unroll
    for (int i = tid; i < 64 * 32; i += 256) {
        int r = i >> 5, c2 = (i & 31) * 2;
        size_t g = (size_t)(b * T_SEQ + tt * 64 + r) * DIM + h * HS + c2;
        *(unsigned*)&S[r][c2] = *(const unsigned*)&V[g];
    }
    __syncthreads();
#pragma unroll
    for (int i = tid; i < 64 * 32; i += 256) {
        int s = i >> 5, t2 = (i & 31) * 2;
        size_t g = (size_t)(bh * HS + s) * T_SEQ + tt * 64 + t2;
        *(unsigned*)&Vt[g] = pkh(S[t2][s], S[t2 + 1][s]);
    }
}

// ---------------- fp16 2-term MMA GEMM, cp.async double-buffered -------------
// C = scale * ((Ah + Al) @ B); Ah/Al fp16 [m][k], Bt single fp16 [n][k].
// modes: 0 = fp32 out; 2 = fp16 single out; 3 = fp16 hi/lo pair out
#define GP 40
#define GEMM_NKT 32
#define GEMM_SMEM (6 * 128 * GP * 2)   // 2 stages x 3 arrays = 61440 B

__global__ __launch_bounds__(256) void gemm_mma(
    const __half* __restrict__ Ah_, const __half* __restrict__ Al_,
    const __half* __restrict__ B_,
    float* __restrict__ Cf, __half* __restrict__ Chh, __half* __restrict__ Chl,
    int mode, float scale) {
    extern __shared__ __half gsm[];
    const int tid = threadIdx.x;
    const int lane = tid & 31, wid = tid >> 5;
    const int gid = lane >> 2, tig = lane & 3;
    const int wm = (wid & 3) * 32, wn = (wid >> 2) * 64;
    const int bm = blockIdx.y * 128, bn = blockIdx.x * 128;

    const __half* srcs[3] = {Ah_, Al_, B_};

    auto load_stage = [&](int stage, int kt) {
        const int k0 = kt * 32;
        __half* sb = gsm + stage * 3 * 128 * GP;
#pragma unroll
        for (int i = tid; i < 1536; i += 256) {
            int a = i >> 9, r = (i >> 2) & 127, c = i & 3;
            const int rbase = (a < 2) ? bm : bn;
            cp16(sb + a * 128 * GP + r * GP + c * 8,
                 srcs[a] + (size_t)(rbase + r) * DIM + k0 + c * 8);
        }
    };

    float acc[2][8][4];
#pragma unroll
    for (int mt = 0; mt < 2; mt++)
#pragma unroll
        for (int jn = 0; jn < 8; jn++)
#pragma unroll
            for (int e = 0; e < 4; e++) acc[mt][jn][e] = 0.f;

    load_stage(0, 0); CP_COMMIT();
    load_stage(1, 1); CP_COMMIT();

    for (int kt = 0; kt < GEMM_NKT; kt++) {
        const int cur = kt & 1;
        CP_WAIT1();
        __syncthreads();
        const __half* As_h = gsm + (cur * 3 + 0) * 128 * GP;
        const __half* As_l = gsm + (cur * 3 + 1) * 128 * GP;
        const __half* Bs   = gsm + (cur * 3 + 2) * 128 * GP;
#pragma unroll
        for (int kk = 0; kk < 2; kk++) {
            const int kc = kk * 16 + 2 * tig;
            unsigned ah[2][4], al[2][4];
#pragma unroll
            for (int mt = 0; mt < 2; mt++) {
                int row = wm + 16 * mt + gid;
                ah[mt][0] = *(const unsigned*)&As_h[row * GP + kc];
                ah[mt][1] = *(const unsigned*)&As_h[(row + 8) * GP + kc];
                ah[mt][2] = *(const unsigned*)&As_h[row * GP + kc + 8];
                ah[mt][3] = *(const unsigned*)&As_h[(row + 8) * GP + kc + 8];
                al[mt][0] = *(const unsigned*)&As_l[row * GP + kc];
                al[mt][1] = *(const unsigned*)&As_l[(row + 8) * GP + kc];
                al[mt][2] = *(const unsigned*)&As_l[row * GP + kc + 8];
                al[mt][3] = *(const unsigned*)&As_l[(row + 8) * GP + kc + 8];
            }
#pragma unroll
            for (int jn = 0; jn < 8; jn++) {
                int n = wn + 8 * jn + gid;
                unsigned b0 = *(const unsigned*)&Bs[n * GP + kc];
                unsigned b1 = *(const unsigned*)&Bs[n * GP + kc + 8];
#pragma unroll
                for (int mt = 0; mt < 2; mt++) {
                    mma16816h(acc[mt][jn], ah[mt], b0, b1);
                    mma16816h(acc[mt][jn], al[mt], b0, b1);
                }
            }
        }
        __syncthreads();
        if (kt + 2 < GEMM_NKT) load_stage(cur, kt + 2);
        CP_COMMIT();
    }

#pragma unroll
    for (int mt = 0; mt < 2; mt++) {
        int row0 = bm + wm + 16 * mt + gid;
#pragma unroll
        for (int jn = 0; jn < 8; jn++) {
            int col = bn + wn + 8 * jn + 2 * tig;
            float x0 = acc[mt][jn][0] * scale, x1 = acc[mt][jn][1] * scale;
            float x2 = acc[mt][jn][2] * scale, x3 = acc[mt][jn][3] * scale;
            if (mode == 0) {
                *(float2*)&Cf[(size_t)row0 * DIM + col] = make_float2(x0, x1);
                *(float2*)&Cf[(size_t)(row0 + 8) * DIM + col] = make_float2(x2, x3);
            } else if (mode == 2) {
                *(unsigned*)&Chh[(size_t)row0 * DIM + col] =
                    pkh(__float2half_rn(x0), __float2half_rn(x1));
                *(unsigned*)&Chh[(size_t)(row0 + 8) * DIM + col] =
                    pkh(__float2half_rn(x2), __float2half_rn(x3));
            } else {
                unsigned ph, pl;
                split_pack2h(x0, x1, ph, pl);
                *(unsigned*)&Chh[(size_t)row0 * DIM + col] = ph;
                *(unsigned*)&Chl[(size_t)row0 * DIM + col] = pl;
                split_pack2h(x2, x3, ph, pl);
                *(unsigned*)&Chh[(size_t)(row0 + 8) * DIM + col] = ph;
                *(unsigned*)&Chl[(size_t)(row0 + 8) * DIM + col] = pl;
            }
        }
    }
}

// ---------------- flash attention: single fp16 everywhere --------------------
// Q single fp16 (resident); K,V single fp16 (streamed, double-buffered).
// QK: 1 MMA per fragment; PV: 1 MMA per fragment (P rounded to fp16).
#define AP 72
#define ATTN_NKT (T_SEQ / 64)
#define ATTN_SMEM ((128 + 2 * 2 * 64) * AP * 2)   // 55296 B

__global__ __launch_bounds__(256) void attn_mma(
    const __half* __restrict__ Q_, const __half* __restrict__ K_,
    const __half* __restrict__ Vt_, const float* __restrict__ mask,
    __half* __restrict__ Oh_, __half* __restrict__ Ol_) {
    extern __shared__ __half asm_[];
    __half* Qs = asm_;                 // [128][AP]
    __half* KV = Qs + 128 * AP;        // stage s: K [64*AP], V [64*AP]

    const int tid = threadIdx.x;
    const int lane = tid & 31, wid = tid >> 5;
    const int gid = lane >> 2, tig = lane & 3;
    const int bq = blockIdx.x, h = blockIdx.y, b = blockIdx.z;
    const int bh = b * NH + h;
    const int qrow0 = b * T_SEQ + bq * 128;

    auto load_kv = [&](int stage, int kt) {
        const int krow0 = b * T_SEQ + kt * 64;
        __half* sb = KV + stage * 2 * 64 * AP;
#pragma unroll
        for (int i = tid; i < 1024; i += 256) {
            int a = i >> 9, r = (i >> 3) & 63, c = i & 7;
            __half* dst = sb + a * 64 * AP + r * AP + c * 8;
            if (a == 0)
                cp16(dst, K_ + (size_t)(krow0 + r) * DIM + h * HS + c * 8);
            else
                cp16(dst, Vt_ + (size_t)(bh * HS + r) * T_SEQ + kt * 64 + c * 8);
        }
    };

#pragma unroll
    for (int i = tid; i < 128 * 8; i += 256) {
        int r = i >> 3, c8 = (i & 7) * 8;
        *(int4*)&Qs[r * AP + c8] =
            *(const int4*)&Q_[(size_t)(qrow0 + r) * DIM + h * HS + c8];
    }

    load_kv(0, 0); CP_COMMIT();
    load_kv(1, 1); CP_COMMIT();

    float mi[2] = {-1e30f, -1e30f}, li[2] = {0.f, 0.f};
    float accO[8][4];
#pragma unroll
    for (int jn = 0; jn < 8; jn++)
#pragma unroll
        for (int e = 0; e < 4; e++) accO[jn][e] = 0.f;

    const int q0g = bq * 128 + 16 * wid + gid;
    const float* mrow = mask + (size_t)bh * T_SEQ * T_SEQ;
    __syncthreads();

    for (int kt = 0; kt < ATTN_NKT; kt++) {
        const int cur = kt & 1;
        CP_WAIT1();
        __syncthreads();
        const __half* K_s = KV + (cur * 2 + 0) * 64 * AP;
        const __half* V_s = KV + (cur * 2 + 1) * 64 * AP;

        // ---- mask prefetch ----
        float2 mr0[8], mr1[8];
#pragma unroll
        for (int jn = 0; jn < 8; jn++) {
            int c = kt * 64 + 8 * jn + 2 * tig;
            mr0[jn] = *(const float2*)&mrow[(size_t)q0g * T_SEQ + c];
            mr1[jn] = *(const float2*)&mrow[(size_t)(q0g + 8) * T_SEQ + c];
        }

        // ---- scores: S = Q @ K^T (single fp16) ----
        float sc[8][4];
#pragma unroll
        for (int jn = 0; jn < 8; jn++)
#pragma unroll
            for (int e = 0; e < 4; e++) sc[jn][e] = 0.f;
#pragma unroll
        for (int kk = 0; kk < 4; kk++) {
            const int kc = kk * 16 + 2 * tig;
            const int row = 16 * wid + gid;
            unsigned qa[4];
            qa[0] = *(const unsigned*)&Qs[row * AP + kc];
            qa[1] = *(const unsigned*)&Qs[(row + 8) * AP + kc];
            qa[2] = *(const unsigned*)&Qs[row * AP + kc + 8];
            qa[3] = *(const unsigned*)&Qs[(row + 8) * AP + kc + 8];
#pragma unroll
            for (int jn = 0; jn < 8; jn++) {
                int n = 8 * jn + gid;
                unsigned kf0 = *(const unsigned*)&K_s[n * AP + kc];
                unsigned kf1 = *(const unsigned*)&K_s[n * AP + kc + 8];
                mma16816h(sc[jn], qa, kf0, kf1);
            }
        }

        // ---- apply mask ----
#pragma unroll
        for (int jn = 0; jn < 8; jn++) {
            sc[jn][0] = fmaf(mr0[jn].x, NEG_INF_F, sc[jn][0]);
            sc[jn][1] = fmaf(mr0[jn].y, NEG_INF_F, sc[jn][1]);
            sc[jn][2] = fmaf(mr1[jn].x, NEG_INF_F, sc[jn][2]);
            sc[jn][3] = fmaf(mr1[jn].y, NEG_INF_F, sc[jn][3]);
        }

        // ---- online softmax ----
        float mx0 = -1e30f, mx1 = -1e30f;
#pragma unroll
        for (int jn = 0; jn < 8; jn++) {
            mx0 = fmaxf(mx0, fmaxf(sc[jn][0], sc[jn][1]));
            mx1 = fmaxf(mx1, fmaxf(sc[jn][2], sc[jn][3]));
        }
        mx0 = fmaxf(mx0, __shfl_xor_sync(0xffffffffu, mx0, 1));
        mx0 = fmaxf(mx0, __shfl_xor_sync(0xffffffffu, mx0, 2));
        mx1 = fmaxf(mx1, __shfl_xor_sync(0xffffffffu, mx1, 1));
        mx1 = fmaxf(mx1, __shfl_xor_sync(0xffffffffu, mx1, 2));
        float mn0 = fmaxf(mi[0], mx0), mn1 = fmaxf(mi[1], mx1);
        float corr0 = __expf(mi[0] - mn0), corr1 = __expf(mi[1] - mn1);
        mi[0] = mn0; mi[1] = mn1;
        float rs0 = 0.f, rs1 = 0.f;
#pragma unroll
        for (int jn = 0; jn < 8; jn++) {
            sc[jn][0] = __expf(sc[jn][0] - mn0); rs0 += sc[jn][0];
            sc[jn][1] = __expf(sc[jn][1] - mn0); rs0 += sc[jn][1];
            sc[jn][2] = __expf(sc[jn][2] - mn1); rs1 += sc[jn][2];
            sc[jn][3] = __expf(sc[jn][3] - mn1); rs1 += sc[jn][3];
        }
        rs0 += __shfl_xor_sync(0xffffffffu, rs0, 1);
        rs0 += __shfl_xor_sync(0xffffffffu, rs0, 2);
        rs1 += __shfl_xor_sync(0xffffffffu, rs1, 1);
        rs1 += __shfl_xor_sync(0xffffffffu, rs1, 2);
        li[0] = li[0] * corr0 + rs0;
        li[1] = li[1] * corr1 + rs1;
#pragma unroll
        for (int jn = 0; jn < 8; jn++) {
            accO[jn][0] *= corr0; accO[jn][1] *= corr0;
            accO[jn][2] *= corr1; accO[jn][3] *= corr1;
        }

        // ---- accO += P @ V (P single fp16) ----
#pragma unroll
        for (int kk2 = 0; kk2 < 4; kk2++) {
            const int j0 = 2 * kk2, j1 = 2 * kk2 + 1;
            unsigned pa[4];
            pa[0] = pkh(__float2half_rn(sc[j0][0]), __float2half_rn(sc[j0][1]));
            pa[1] = pkh(__float2half_rn(sc[j0][2]), __float2half_rn(sc[j0][3]));
            pa[2] = pkh(__float2half_rn(sc[j1][0]), __float2half_rn(sc[j1][1]));
            pa[3] = pkh(__float2half_rn(sc[j1][2]), __float2half_rn(sc[j1][3]));
            const int kc = kk2 * 16 + 2 * tig;
#pragma unroll
            for (int jn = 0; jn < 8; jn++) {
                int n = 8 * jn + gid;
                unsigned vf0 = *(const unsigned*)&V_s[n * AP + kc];
                unsigned vf1 = *(const unsigned*)&V_s[n * AP + kc + 8];
                mma16816h(accO[jn], pa, vf0, vf1);
            }
        }
        __syncthreads();
        if (kt + 2 < ATTN_NKT) load_kv(cur, kt + 2);
        CP_COMMIT();
    }

    // ---- epilogue: normalize, fp16 hi/lo pair for out-projection ----
    const float inv0 = 1.f / li[0], inv1 = 1.f / li[1];
    const int row0 = qrow0 + 16 * wid + gid;
#pragma unroll
    for (int jn = 0; jn < 8; jn++) {
        int col = h * HS + 8 * jn + 2 * tig;
        unsigned ph, pl;
        split_pack2h(accO[jn][0] * inv0, accO[jn][1] * inv0, ph, pl);
        *(unsigned*)&Oh_[(size_t)row0 * DIM + col] = ph;
        *(unsigned*)&Ol_[(size_t)row0 * DIM + col] = pl;
        split_pack2h(accO[jn][2] * inv1, accO[jn][3] * inv1, ph, pl);
        *(unsigned*)&Oh_[(size_t)(row0 + 8) * DIM + col] = ph;
        *(unsigned*)&Ol_[(size_t)(row0 + 8) * DIM + col] = pl;
    }
}

// ---------------------------------------------------------------------------
extern "C" void kernel_launch(void* const* d_in, const int* in_sizes, int n_in,
                              void* d_out, int out_size) {
    const float* Xq   = (const float*)d_in[0];
    const float* Xr   = (const float*)d_in[1];
    const float* mask = (const float*)d_in[2];
    const float* Wq   = (const float*)d_in[3];
    const float* Wk   = (const float*)d_in[4];
    const float* Wv   = (const float*)d_in[5];
    const float* Wo   = (const float*)d_in[6];
    float* out = (float*)d_out;

    __half *Xqh, *Xql, *Xrh, *Xrl, *WqT, *WkT, *WvT, *WoT;
    __half *Q16, *K16, *V16, *Vt16, *O16h, *O16l;
    cudaGetSymbolAddress((void**)&Xqh, g_Xqh);   cudaGetSymbolAddress((void**)&Xql, g_Xql);
    cudaGetSymbolAddress((void**)&Xrh, g_Xrh);   cudaGetSymbolAddress((void**)&Xrl, g_Xrl);
    cudaGetSymbolAddress((void**)&WqT, g_WqT);   cudaGetSymbolAddress((void**)&WkT, g_WkT);
    cudaGetSymbolAddress((void**)&WvT, g_WvT);   cudaGetSymbolAddress((void**)&WoT, g_WoT);
    cudaGetSymbolAddress((void**)&Q16, g_Q16);   cudaGetSymbolAddress((void**)&K16, g_K16);
    cudaGetSymbolAddress((void**)&V16, g_V16);   cudaGetSymbolAddress((void**)&Vt16, g_Vt16);
    cudaGetSymbolAddress((void**)&O16h, g_O16h); cudaGetSymbolAddress((void**)&O16l, g_O16l);

    cudaFuncSetAttribute(attn_mma, cudaFuncAttributeMaxDynamicSharedMemorySize, ATTN_SMEM);
    cudaFuncSetAttribute(gemm_mma, cudaFuncAttributeMaxDynamicSharedMemorySize, GEMM_SMEM);

    // 1) split inputs
    split_x<<<NELEM / 1024, 256>>>(Xq, Xqh, Xql);
    split_x<<<NELEM / 1024, 256>>>(Xr, Xrh, Xrl);
    dim3 gw(32, 32);
    split_wT<<<gw, 256>>>(Wq, WqT);
    split_wT<<<gw, 256>>>(Wk, WkT);
    split_wT<<<gw, 256>>>(Wv, WvT);
    split_wT<<<gw, 256>>>(Wo, WoT);

    // 2) projections (fp16 2-term), outputs single fp16
    dim3 gg(DIM / 128, NT_ROWS / 128);
    gemm_mma<<<gg, 256, GEMM_SMEM>>>(Xqh, Xql, WqT, nullptr, Q16, nullptr, 2, 0.125f);
    gemm_mma<<<gg, 256, GEMM_SMEM>>>(Xrh, Xrl, WkT, nullptr, K16, nullptr, 2, 1.0f);
    gemm_mma<<<gg, 256, GEMM_SMEM>>>(Xrh, Xrl, WvT, nullptr, V16, nullptr, 2, 1.0f);

    // 3) V transpose
    transpose_v<<<dim3(T_SEQ / 64, NB * NH), 256>>>(V16, Vt16);

    // 4) flash attention (single fp16)
    attn_mma<<<dim3(T_SEQ / 128, NH, NB), 256, ATTN_SMEM>>>(
        Q16, K16, Vt16, mask, O16h, O16l);

    // 5) output projection (O pair x Wo single) -> fp32 d_out
    gemm_mma<<<gg, 256, GEMM_SMEM>>>(O16h, O16l, WoT, out, nullptr, nullptr, 0, 1.0f);
}

// round 8
// speedup vs baseline: 1.6126x; 1.0115x over previous
#include <cuda_runtime.h>
#include <cuda_fp16.h>
#include <cstdint>

#define T_SEQ 2048
#define NB 2
#define DIM 1024
#define NH 16
#define HS 64
#define NT_ROWS 4096
#define NEG_INF_F (-1e9f)
#define NELEM (NT_ROWS * DIM)

// ---------------- scratch (__device__ globals: allocation-free rule) --------
__device__ __half g_Xqh[NELEM], g_Xql[NELEM];
__device__ __half g_Xrh[NELEM], g_Xrl[NELEM];
__device__ __half g_WqT[DIM * DIM];
__device__ __half g_WkT[DIM * DIM];
__device__ __half g_WvT[DIM * DIM];
__device__ __half g_WoT[DIM * DIM];
__device__ __half g_Q16[NELEM];
__device__ __half g_K16[NELEM];
__device__ __half g_V16[NELEM];
__device__ __half g_Vt16[NELEM];
__device__ __half g_O16h[NELEM], g_O16l[NELEM];

// ---------------- helpers ---------------------------------------------------
__device__ __forceinline__ unsigned pkh(__half a, __half b) {
    return (unsigned)__half_as_ushort(a) | ((unsigned)__half_as_ushort(b) << 16);
}
__device__ __forceinline__ void split2h(float x, __half& h, __half& l) {
    h = __float2half_rn(x);
    l = __float2half_rn(x - __half2float(h));
}
__device__ __forceinline__ void split_pack2h(float x0, float x1, unsigned& ph, unsigned& pl) {
    __half h0, l0, h1, l1;
    split2h(x0, h0, l0);
    split2h(x1, h1, l1);
    ph = pkh(h0, h1);
    pl = pkh(l0, l1);
}
__device__ __forceinline__ void mma16816h(float (&d)[4], const unsigned (&a)[4],
                                          unsigned b0, unsigned b1) {
    asm volatile(
        "mma.sync.aligned.m16n8k16.row.col.f32.f16.f16.f32 "
        "{%0,%1,%2,%3}, {%4,%5,%6,%7}, {%8,%9}, {%0,%1,%2,%3};"
        : "+f"(d[0]), "+f"(d[1]), "+f"(d[2]), "+f"(d[3])
        : "r"(a[0]), "r"(a[1]), "r"(a[2]), "r"(a[3]), "r"(b0), "r"(b1));
}
__device__ __forceinline__ uint32_t smem_u32(const void* p) {
    uint32_t a;
    asm("{ .reg .u64 t; cvta.to.shared.u64 t, %1; cvt.u32.u64 %0, t; }" : "=r"(a) : "l"(p));
    return a;
}
__device__ __forceinline__ void cp16(void* smem_dst, const void* gsrc) {
    uint32_t s = smem_u32(smem_dst);
    asm volatile("cp.async.cg.shared.global [%0], [%1], 16;" :: "r"(s), "l"(gsrc) : "memory");
}
#define CP_COMMIT() asm volatile("cp.async.commit_group;" ::: "memory")
#define CP_WAIT2() asm volatile("cp.async.wait_group 2;" ::: "memory")
#define CP_WAIT3() asm volatile("cp.async.wait_group 3;" ::: "memory")

// ---------------- split kernels (merged) -------------------------------------
// z = 0: Xq -> Xqh/Xql ; z = 1: Xr -> Xrh/Xrl
__global__ __launch_bounds__(256) void split_x_all(
    const float* __restrict__ Xq, const float* __restrict__ Xr,
    __half* __restrict__ Xqh, __half* __restrict__ Xql,
    __half* __restrict__ Xrh, __half* __restrict__ Xrl) {
    const int z = blockIdx.y;
    const float* X = z ? Xr : Xq;
    __half* Xh = z ? Xrh : Xqh;
    __half* Xl = z ? Xrl : Xql;
    size_t i = ((size_t)blockIdx.x * 256 + threadIdx.x) * 4;
    float4 v = *(const float4*)(X + i);
    unsigned ph0, pl0, ph1, pl1;
    split_pack2h(v.x, v.y, ph0, pl0);
    split_pack2h(v.z, v.w, ph1, pl1);
    *(unsigned*)&Xh[i]     = ph0;
    *(unsigned*)&Xh[i + 2] = ph1;
    *(unsigned*)&Xl[i]     = pl0;
    *(unsigned*)&Xl[i + 2] = pl1;
}

// z selects which W; output transposed single fp16
__global__ __launch_bounds__(256) void split_wT_all(
    const float* __restrict__ W0, const float* __restrict__ W1,
    const float* __restrict__ W2, const float* __restrict__ W3,
    __half* __restrict__ T0, __half* __restrict__ T1,
    __half* __restrict__ T2, __half* __restrict__ T3) {
    const int z = blockIdx.z;
    const float* W = (z == 0) ? W0 : (z == 1) ? W1 : (z == 2) ? W2 : W3;
    __half* Wt = (z == 0) ? T0 : (z == 1) ? T1 : (z == 2) ? T2 : T3;
    __shared__ float S[32][33];
    const int n0 = blockIdx.x * 32, k0 = blockIdx.y * 32;
    const int tid = threadIdx.x;
#pragma unroll
    for (int i = tid; i < 1024; i += 256) {
        int r = i >> 5, c = i & 31;
        S[r][c] = W[(size_t)(k0 + r) * DIM + n0 + c];
    }
    __syncthreads();
#pragma unroll
    for (int i = tid; i < 1024; i += 256) {
        int rr = i >> 5, cc = i & 31;
        Wt[(size_t)(n0 + rr) * DIM + k0 + cc] = __float2half_rn(S[cc][rr]);
    }
}

__global__ __launch_bounds__(256) void transpose_v(const __half* __restrict__ V,
                                                   __half* __restrict__ Vt) {
    __shared__ __half S[64][66];
    const int tt = blockIdx.x, bh = blockIdx.y;
    const int b = bh >> 4, h = bh & 15;
    const int tid = threadIdx.x;
#pragma unroll
    for (int i = tid; i < 64 * 32; i += 256) {
        int r = i >> 5, c2 = (i & 31) * 2;
        size_t g = (size_t)(b * T_SEQ + tt * 64 + r) * DIM + h * HS + c2;
        *(unsigned*)&S[r][c2] = *(const unsigned*)&V[g];
    }
    __syncthreads();
#pragma unroll
    for (int i = tid; i < 64 * 32; i += 256) {
        int s = i >> 5, t2 = (i & 31) * 2;
        size_t g = (size_t)(bh * HS + s) * T_SEQ + tt * 64 + t2;
        *(unsigned*)&Vt[g] = pkh(S[t2][s], S[t2 + 1][s]);
    }
}

// ---------------- fp16 2-term GEMM, 3-stage cp.async pipeline ----------------
// C = scale * ((Ah + Al) @ B); modes: 0 fp32 out; 2 fp16 single out
#define GP 40
#define GEMM_NKT 32
#define GEMM_STAGE (3 * 128 * GP)           // halfs per stage
#define GEMM_SMEM (3 * GEMM_STAGE * 2)      // 92160 B

__global__ __launch_bounds__(256) void gemm_mma(
    const __half* __restrict__ Ah_, const __half* __restrict__ Al_,
    const __half* __restrict__ B_,
    float* __restrict__ Cf, __half* __restrict__ Chh, __half* __restrict__ Chl,
    int mode, float scale) {
    extern __shared__ __half gsm[];
    const int tid = threadIdx.x;
    const int lane = tid & 31, wid = tid >> 5;
    const int gid = lane >> 2, tig = lane & 3;
    const int wm = (wid & 3) * 32, wn = (wid >> 2) * 64;
    const int bm = blockIdx.y * 128, bn = blockIdx.x * 128;

    const __half* srcs[3] = {Ah_, Al_, B_};

    auto load_stage = [&](int stage, int kt) {
        const int k0 = kt * 32;
        __half* sb = gsm + stage * GEMM_STAGE;
#pragma unroll
        for (int i = tid; i < 1536; i += 256) {
            int a = i >> 9, r = (i >> 2) & 127, c = i & 3;
            const int rbase = (a < 2) ? bm : bn;
            cp16(sb + a * 128 * GP + r * GP + c * 8,
                 srcs[a] + (size_t)(rbase + r) * DIM + k0 + c * 8);
        }
    };

    float acc[2][8][4];
#pragma unroll
    for (int mt = 0; mt < 2; mt++)
#pragma unroll
        for (int jn = 0; jn < 8; jn++)
#pragma unroll
            for (int e = 0; e < 4; e++) acc[mt][jn][e] = 0.f;

    load_stage(0, 0); CP_COMMIT();
    load_stage(1, 1); CP_COMMIT();

    for (int kt = 0; kt < GEMM_NKT; kt++) {
        // issue prefetch for kt+2 FIRST (its buffer was consumed at kt-1;
        // end-of-iteration barrier makes the overwrite safe)
        if (kt + 2 < GEMM_NKT) load_stage((kt + 2) % 3, kt + 2);
        CP_COMMIT();
        CP_WAIT2();          // group kt complete
        __syncthreads();

        const __half* st = gsm + (kt % 3) * GEMM_STAGE;
        const __half* As_h = st;
        const __half* As_l = st + 128 * GP;
        const __half* Bs   = st + 2 * 128 * GP;
#pragma unroll
        for (int kk = 0; kk < 2; kk++) {
            const int kc = kk * 16 + 2 * tig;
            unsigned ah[2][4], al[2][4];
#pragma unroll
            for (int mt = 0; mt < 2; mt++) {
                int row = wm + 16 * mt + gid;
                ah[mt][0] = *(const unsigned*)&As_h[row * GP + kc];
                ah[mt][1] = *(const unsigned*)&As_h[(row + 8) * GP + kc];
                ah[mt][2] = *(const unsigned*)&As_h[row * GP + kc + 8];
                ah[mt][3] = *(const unsigned*)&As_h[(row + 8) * GP + kc + 8];
                al[mt][0] = *(const unsigned*)&As_l[row * GP + kc];
                al[mt][1] = *(const unsigned*)&As_l[(row + 8) * GP + kc];
                al[mt][2] = *(const unsigned*)&As_l[row * GP + kc + 8];
                al[mt][3] = *(const unsigned*)&As_l[(row + 8) * GP + kc + 8];
            }
#pragma unroll
            for (int jn = 0; jn < 8; jn++) {
                int n = wn + 8 * jn + gid;
                unsigned b0 = *(const unsigned*)&Bs[n * GP + kc];
                unsigned b1 = *(const unsigned*)&Bs[n * GP + kc + 8];
#pragma unroll
                for (int mt = 0; mt < 2; mt++) {
                    mma16816h(acc[mt][jn], ah[mt], b0, b1);
                    mma16816h(acc[mt][jn], al[mt], b0, b1);
                }
            }
        }
        __syncthreads();     // all warps done with buffer kt%3
    }

#pragma unroll
    for (int mt = 0; mt < 2; mt++) {
        int row0 = bm + wm + 16 * mt + gid;
#pragma unroll
        for (int jn = 0; jn < 8; jn++) {
            int col = bn + wn + 8 * jn + 2 * tig;
            float x0 = acc[mt][jn][0] * scale, x1 = acc[mt][jn][1] * scale;
            float x2 = acc[mt][jn][2] * scale, x3 = acc[mt][jn][3] * scale;
            if (mode == 0) {
                *(float2*)&Cf[(size_t)row0 * DIM + col] = make_float2(x0, x1);
                *(float2*)&Cf[(size_t)(row0 + 8) * DIM + col] = make_float2(x2, x3);
            } else {
                *(unsigned*)&Chh[(size_t)row0 * DIM + col] =
                    pkh(__float2half_rn(x0), __float2half_rn(x1));
                *(unsigned*)&Chh[(size_t)(row0 + 8) * DIM + col] =
                    pkh(__float2half_rn(x2), __float2half_rn(x3));
            }
        }
    }
    (void)Chl;
}

// ---------------- flash attention: single fp16, 4-stage KV pipeline ----------
#define AP 72
#define ATTN_NKT (T_SEQ / 64)
#define KV_STAGE (2 * 64 * AP)                       // halfs per stage
#define ATTN_SMEM ((128 * AP + 4 * KV_STAGE) * 2)    // 92160 B

__global__ __launch_bounds__(256) void attn_mma(
    const __half* __restrict__ Q_, const __half* __restrict__ K_,
    const __half* __restrict__ Vt_, const float* __restrict__ mask,
    __half* __restrict__ Oh_, __half* __restrict__ Ol_) {
    extern __shared__ __half asm_[];
    __half* Qs = asm_;
    __half* KV = Qs + 128 * AP;

    const int tid = threadIdx.x;
    const int lane = tid & 31, wid = tid >> 5;
    const int gid = lane >> 2, tig = lane & 3;
    const int bq = blockIdx.x, h = blockIdx.y, b = blockIdx.z;
    const int bh = b * NH + h;
    const int qrow0 = b * T_SEQ + bq * 128;

    auto load_kv = [&](int stage, int kt) {
        const int krow0 = b * T_SEQ + kt * 64;
        __half* sb = KV + stage * KV_STAGE;
#pragma unroll
        for (int i = tid; i < 1024; i += 256) {
            int a = i >> 9, r = (i >> 3) & 63, c = i & 7;
            __half* dst = sb + a * 64 * AP + r * AP + c * 8;
            if (a == 0)
                cp16(dst, K_ + (size_t)(krow0 + r) * DIM + h * HS + c * 8);
            else
                cp16(dst, Vt_ + (size_t)(bh * HS + r) * T_SEQ + kt * 64 + c * 8);
        }
    };

#pragma unroll
    for (int i = tid; i < 128 * 8; i += 256) {
        int r = i >> 3, c8 = (i & 7) * 8;
        *(int4*)&Qs[r * AP + c8] =
            *(const int4*)&Q_[(size_t)(qrow0 + r) * DIM + h * HS + c8];
    }

    load_kv(0, 0); CP_COMMIT();
    load_kv(1, 1); CP_COMMIT();
    load_kv(2, 2); CP_COMMIT();

    float mi[2] = {-1e30f, -1e30f}, li[2] = {0.f, 0.f};
    float accO[8][4];
#pragma unroll
    for (int jn = 0; jn < 8; jn++)
#pragma unroll
        for (int e = 0; e < 4; e++) accO[jn][e] = 0.f;

    const int q0g = bq * 128 + 16 * wid + gid;
    const float* mrow = mask + (size_t)bh * T_SEQ * T_SEQ;
    __syncthreads();   // Q visible

    for (int kt = 0; kt < ATTN_NKT; kt++) {
        // prefetch kt+3 (buffer consumed at kt-1; end barrier makes it safe)
        if (kt + 3 < ATTN_NKT) load_kv((kt + 3) & 3, kt + 3);
        CP_COMMIT();

        // ---- mask prefetch (independent of cp.async wait) ----
        float2 mr0[8], mr1[8];
#pragma unroll
        for (int jn = 0; jn < 8; jn++) {
            int c = kt * 64 + 8 * jn + 2 * tig;
            mr0[jn] = *(const float2*)&mrow[(size_t)q0g * T_SEQ + c];
            mr1[jn] = *(const float2*)&mrow[(size_t)(q0g + 8) * T_SEQ + c];
        }

        CP_WAIT3();
        __syncthreads();
        const __half* K_s = KV + (kt & 3) * KV_STAGE;
        const __half* V_s = K_s + 64 * AP;

        // ---- scores: S = Q @ K^T ----
        float sc[8][4];
#pragma unroll
        for (int jn = 0; jn < 8; jn++)
#pragma unroll
            for (int e = 0; e < 4; e++) sc[jn][e] = 0.f;
#pragma unroll
        for (int kk = 0; kk < 4; kk++) {
            const int kc = kk * 16 + 2 * tig;
            const int row = 16 * wid + gid;
            unsigned qa[4];
            qa[0] = *(const unsigned*)&Qs[row * AP + kc];
            qa[1] = *(const unsigned*)&Qs[(row + 8) * AP + kc];
            qa[2] = *(const unsigned*)&Qs[row * AP + kc + 8];
            qa[3] = *(const unsigned*)&Qs[(row + 8) * AP + kc + 8];
#pragma unroll
            for (int jn = 0; jn < 8; jn++) {
                int n = 8 * jn + gid;
                unsigned kf0 = *(const unsigned*)&K_s[n * AP + kc];
                unsigned kf1 = *(const unsigned*)&K_s[n * AP + kc + 8];
                mma16816h(sc[jn], qa, kf0, kf1);
            }
        }

        // ---- apply mask ----
#pragma unroll
        for (int jn = 0; jn < 8; jn++) {
            sc[jn][0] = fmaf(mr0[jn].x, NEG_INF_F, sc[jn][0]);
            sc[jn][1] = fmaf(mr0[jn].y, NEG_INF_F, sc[jn][1]);
            sc[jn][2] = fmaf(mr1[jn].x, NEG_INF_F, sc[jn][2]);
            sc[jn][3] = fmaf(mr1[jn].y, NEG_INF_F, sc[jn][3]);
        }

        // ---- online softmax ----
        float mx0 = -1e30f, mx1 = -1e30f;
#pragma unroll
        for (int jn = 0; jn < 8; jn++) {
            mx0 = fmaxf(mx0, fmaxf(sc[jn][0], sc[jn][1]));
            mx1 = fmaxf(mx1, fmaxf(sc[jn][2], sc[jn][3]));
        }
        mx0 = fmaxf(mx0, __shfl_xor_sync(0xffffffffu, mx0, 1));
        mx0 = fmaxf(mx0, __shfl_xor_sync(0xffffffffu, mx0, 2));
        mx1 = fmaxf(mx1, __shfl_xor_sync(0xffffffffu, mx1, 1));
        mx1 = fmaxf(mx1, __shfl_xor_sync(0xffffffffu, mx1, 2));
        float mn0 = fmaxf(mi[0], mx0), mn1 = fmaxf(mi[1], mx1);
        float corr0 = __expf(mi[0] - mn0), corr1 = __expf(mi[1] - mn1);
        mi[0] = mn0; mi[1] = mn1;
        float rs0 = 0.f, rs1 = 0.f;
#pragma unroll
        for (int jn = 0; jn < 8; jn++) {
            sc[jn][0] = __expf(sc[jn][0] - mn0); rs0 += sc[jn][0];
            sc[jn][1] = __expf(sc[jn][1] - mn0); rs0 += sc[jn][1];
            sc[jn][2] = __expf(sc[jn][2] - mn1); rs1 += sc[jn][2];
            sc[jn][3] = __expf(sc[jn][3] - mn1); rs1 += sc[jn][3];
        }
        rs0 += __shfl_xor_sync(0xffffffffu, rs0, 1);
        rs0 += __shfl_xor_sync(0xffffffffu, rs0, 2);
        rs1 += __shfl_xor_sync(0xffffffffu, rs1, 1);
        rs1 += __shfl_xor_sync(0xffffffffu, rs1, 2);
        li[0] = li[0] * corr0 + rs0;
        li[1] = li[1] * corr1 + rs1;
#pragma unroll
        for (int jn = 0; jn < 8; jn++) {
            accO[jn][0] *= corr0; accO[jn][1] *= corr0;
            accO[jn][2] *= corr1; accO[jn][3] *= corr1;
        }

        // ---- accO += P @ V ----
#pragma unroll
        for (int kk2 = 0; kk2 < 4; kk2++) {
            const int j0 = 2 * kk2, j1 = 2 * kk2 + 1;
            unsigned pa[4];
            pa[0] = pkh(__float2half_rn(sc[j0][0]), __float2half_rn(sc[j0][1]));
            pa[1] = pkh(__float2half_rn(sc[j0][2]), __float2half_rn(sc[j0][3]));
            pa[2] = pkh(__float2half_rn(sc[j1][0]), __float2half_rn(sc[j1][1]));
            pa[3] = pkh(__float2half_rn(sc[j1][2]), __float2half_rn(sc[j1][3]));
            const int kc = kk2 * 16 + 2 * tig;
#pragma unroll
            for (int jn = 0; jn < 8; jn++) {
                int n = 8 * jn + gid;
                unsigned vf0 = *(const unsigned*)&V_s[n * AP + kc];
                unsigned vf1 = *(const unsigned*)&V_s[n * AP + kc + 8];
                mma16816h(accO[jn], pa, vf0, vf1);
            }
        }
        __syncthreads();   // all warps done with buffer kt&3
    }

    // ---- epilogue ----
    const float inv0 = 1.f / li[0], inv1 = 1.f / li[1];
    const int row0 = qrow0 + 16 * wid + gid;
#pragma unroll
    for (int jn = 0; jn < 8; jn++) {
        int col = h * HS + 8 * jn + 2 * tig;
        unsigned ph, pl;
        split_pack2h(accO[jn][0] * inv0, accO[jn][1] * inv0, ph, pl);
        *(unsigned*)&Oh_[(size_t)row0 * DIM + col] = ph;
        *(unsigned*)&Ol_[(size_t)row0 * DIM + col] = pl;
        split_pack2h(accO[jn][2] * inv1, accO[jn][3] * inv1, ph, pl);
        *(unsigned*)&Oh_[(size_t)(row0 + 8) * DIM + col] = ph;
        *(unsigned*)&Ol_[(size_t)(row0 + 8) * DIM + col] = pl;
    }
}

// ---------------------------------------------------------------------------
extern "C" void kernel_launch(void* const* d_in, const int* in_sizes, int n_in,
                              void* d_out, int out_size) {
    const float* Xq   = (const float*)d_in[0];
    const float* Xr   = (const float*)d_in[1];
    const float* mask = (const float*)d_in[2];
    const float* Wq   = (const float*)d_in[3];
    const float* Wk   = (const float*)d_in[4];
    const float* Wv   = (const float*)d_in[5];
    const float* Wo   = (const float*)d_in[6];
    float* out = (float*)d_out;

    __half *Xqh, *Xql, *Xrh, *Xrl, *WqT, *WkT, *WvT, *WoT;
    __half *Q16, *K16, *V16, *Vt16, *O16h, *O16l;
    cudaGetSymbolAddress((void**)&Xqh, g_Xqh);   cudaGetSymbolAddress((void**)&Xql, g_Xql);
    cudaGetSymbolAddress((void**)&Xrh, g_Xrh);   cudaGetSymbolAddress((void**)&Xrl, g_Xrl);
    cudaGetSymbolAddress((void**)&WqT, g_WqT);   cudaGetSymbolAddress((void**)&WkT, g_WkT);
    cudaGetSymbolAddress((void**)&WvT, g_WvT);   cudaGetSymbolAddress((void**)&WoT, g_WoT);
    cudaGetSymbolAddress((void**)&Q16, g_Q16);   cudaGetSymbolAddress((void**)&K16, g_K16);
    cudaGetSymbolAddress((void**)&V16, g_V16);   cudaGetSymbolAddress((void**)&Vt16, g_Vt16);
    cudaGetSymbolAddress((void**)&O16h, g_O16h); cudaGetSymbolAddress((void**)&O16l, g_O16l);

    cudaFuncSetAttribute(attn_mma, cudaFuncAttributeMaxDynamicSharedMemorySize, ATTN_SMEM);
    cudaFuncSetAttribute(gemm_mma, cudaFuncAttributeMaxDynamicSharedMemorySize, GEMM_SMEM);

    dim3 gg(DIM / 128, NT_ROWS / 128);

    // launch order chosen so ncu (-s 5 -c 1) profiles gemm_mma(Q) at index 5
    split_x_all<<<dim3(NELEM / 1024, 2), 256>>>(Xq, Xr, Xqh, Xql, Xrh, Xrl);      // 0
    split_wT_all<<<dim3(32, 32, 4), 256>>>(Wq, Wk, Wv, Wo, WqT, WkT, WvT, WoT);   // 1
    gemm_mma<<<gg, 256, GEMM_SMEM>>>(Xrh, Xrl, WkT, nullptr, K16, nullptr, 2, 1.0f);   // 2
    gemm_mma<<<gg, 256, GEMM_SMEM>>>(Xrh, Xrl, WvT, nullptr, V16, nullptr, 2, 1.0f);   // 3
    transpose_v<<<dim3(T_SEQ / 64, NB * NH), 256>>>(V16, Vt16);                         // 4
    gemm_mma<<<gg, 256, GEMM_SMEM>>>(Xqh, Xql, WqT, nullptr, Q16, nullptr, 2, 0.125f); // 5 <- ncu
    attn_mma<<<dim3(T_SEQ / 128, NH, NB), 256, ATTN_SMEM>>>(
        Q16, K16, Vt16, mask, O16h, O16l);                                              // 6
    gemm_mma<<<gg, 256, GEMM_SMEM>>>(O16h, O16l, WoT, out, nullptr, nullptr, 0, 1.0f); // 7
}

// round 9
// speedup vs baseline: 1.6148x; 1.0013x over previous
#include <cuda_runtime.h>
#include <cuda_fp16.h>
#include <cstdint>

#define T_SEQ 2048
#define NB 2
#define DIM 1024
#define NH 16
#define HS 64
#define NT_ROWS 4096
#define NEG_INF_F (-1e9f)
#define NELEM (NT_ROWS * DIM)

// ---------------- scratch (__device__ globals: allocation-free rule) --------
__device__ __half g_Xqh[NELEM], g_Xql[NELEM];
__device__ __half g_Xrh[NELEM], g_Xrl[NELEM];
__device__ __half g_WqT[DIM * DIM];
__device__ __half g_WkT[DIM * DIM];
__device__ __half g_WvT[DIM * DIM];
__device__ __half g_WoT[DIM * DIM];
__device__ __half g_Q16[NELEM];
__device__ __half g_K16[NELEM];
__device__ __half g_V16[NELEM];
__device__ __half g_Vt16[NELEM];
__device__ __half g_O16h[NELEM], g_O16l[NELEM];

// ---------------- helpers ---------------------------------------------------
__device__ __forceinline__ unsigned pkh(__half a, __half b) {
    return (unsigned)__half_as_ushort(a) | ((unsigned)__half_as_ushort(b) << 16);
}
__device__ __forceinline__ void split2h(float x, __half& h, __half& l) {
    h = __float2half_rn(x);
    l = __float2half_rn(x - __half2float(h));
}
__device__ __forceinline__ void split_pack2h(float x0, float x1, unsigned& ph, unsigned& pl) {
    __half h0, l0, h1, l1;
    split2h(x0, h0, l0);
    split2h(x1, h1, l1);
    ph = pkh(h0, h1);
    pl = pkh(l0, l1);
}
__device__ __forceinline__ void mma16816h(float (&d)[4], const unsigned (&a)[4],
                                          unsigned b0, unsigned b1) {
    asm volatile(
        "mma.sync.aligned.m16n8k16.row.col.f32.f16.f16.f32 "
        "{%0,%1,%2,%3}, {%4,%5,%6,%7}, {%8,%9}, {%0,%1,%2,%3};"
        : "+f"(d[0]), "+f"(d[1]), "+f"(d[2]), "+f"(d[3])
        : "r"(a[0]), "r"(a[1]), "r"(a[2]), "r"(a[3]), "r"(b0), "r"(b1));
}
__device__ __forceinline__ uint32_t smem_u32(const void* p) {
    uint32_t a;
    asm("{ .reg .u64 t; cvta.to.shared.u64 t, %1; cvt.u32.u64 %0, t; }" : "=r"(a) : "l"(p));
    return a;
}
__device__ __forceinline__ void cp16(void* smem_dst, const void* gsrc) {
    uint32_t s = smem_u32(smem_dst);
    asm volatile("cp.async.cg.shared.global [%0], [%1], 16;" :: "r"(s), "l"(gsrc) : "memory");
}
#define CP_COMMIT() asm volatile("cp.async.commit_group;" ::: "memory")
#define CP_WAIT2() asm volatile("cp.async.wait_group 2;" ::: "memory")
#define CP_WAIT3() asm volatile("cp.async.wait_group 3;" ::: "memory")

// ---------------- split kernels (merged) -------------------------------------
__global__ __launch_bounds__(256) void split_x_all(
    const float* __restrict__ Xq, const float* __restrict__ Xr,
    __half* __restrict__ Xqh, __half* __restrict__ Xql,
    __half* __restrict__ Xrh, __half* __restrict__ Xrl) {
    const int z = blockIdx.y;
    const float* X = z ? Xr : Xq;
    __half* Xh = z ? Xrh : Xqh;
    __half* Xl = z ? Xrl : Xql;
    size_t i = ((size_t)blockIdx.x * 256 + threadIdx.x) * 4;
    float4 v = *(const float4*)(X + i);
    unsigned ph0, pl0, ph1, pl1;
    split_pack2h(v.x, v.y, ph0, pl0);
    split_pack2h(v.z, v.w, ph1, pl1);
    *(unsigned*)&Xh[i]     = ph0;
    *(unsigned*)&Xh[i + 2] = ph1;
    *(unsigned*)&Xl[i]     = pl0;
    *(unsigned*)&Xl[i + 2] = pl1;
}

__global__ __launch_bounds__(256) void split_wT_all(
    const float* __restrict__ W0, const float* __restrict__ W1,
    const float* __restrict__ W2, const float* __restrict__ W3,
    __half* __restrict__ T0, __half* __restrict__ T1,
    __half* __restrict__ T2, __half* __restrict__ T3) {
    const int z = blockIdx.z;
    const float* W = (z == 0) ? W0 : (z == 1) ? W1 : (z == 2) ? W2 : W3;
    __half* Wt = (z == 0) ? T0 : (z == 1) ? T1 : (z == 2) ? T2 : T3;
    __shared__ float S[32][33];
    const int n0 = blockIdx.x * 32, k0 = blockIdx.y * 32;
    const int tid = threadIdx.x;
#pragma unroll
    for (int i = tid; i < 1024; i += 256) {
        int r = i >> 5, c = i & 31;
        S[r][c] = W[(size_t)(k0 + r) * DIM + n0 + c];
    }
    __syncthreads();
#pragma unroll
    for (int i = tid; i < 1024; i += 256) {
        int rr = i >> 5, cc = i & 31;
        Wt[(size_t)(n0 + rr) * DIM + k0 + cc] = __float2half_rn(S[cc][rr]);
    }
}

__global__ __launch_bounds__(256) void transpose_v(const __half* __restrict__ V,
                                                   __half* __restrict__ Vt) {
    __shared__ __half S[64][66];
    const int tt = blockIdx.x, bh = blockIdx.y;
    const int b = bh >> 4, h = bh & 15;
    const int tid = threadIdx.x;
#pragma unroll
    for (int i = tid; i < 64 * 32; i += 256) {
        int r = i >> 5, c2 = (i & 31) * 2;
        size_t g = (size_t)(b * T_SEQ + tt * 64 + r) * DIM + h * HS + c2;
        *(unsigned*)&S[r][c2] = *(const unsigned*)&V[g];
    }
    __syncthreads();
#pragma unroll
    for (int i = tid; i < 64 * 32; i += 256) {
        int s = i >> 5, t2 = (i & 31) * 2;
        size_t g = (size_t)(bh * HS + s) * T_SEQ + tt * 64 + t2;
        *(unsigned*)&Vt[g] = pkh(S[t2][s], S[t2 + 1][s]);
    }
}

// ---------------- fp16 2-term GEMM: 128x256x32 tile, 512 thr, 3-stage --------
// C = scale * ((Ah + Al) @ B). 16 warps: wm = (wid&3)*32, wn = (wid>>2)*64.
// Per-warp structure identical to R8 (bit-identical accumulation).
// Grid (DIM/256, NT_ROWS/128) = (4, 32) = 128 CTAs = one full wave.
#define GP 40
#define GEMM_NKT 32
#define GEMM_STAGE (512 * GP)               // Ah 128 + Al 128 + B 256 rows
#define GEMM_SMEM (3 * GEMM_STAGE * 2)      // 122880 B

__global__ __launch_bounds__(512, 1) void gemm_mma(
    const __half* __restrict__ Ah_, const __half* __restrict__ Al_,
    const __half* __restrict__ B_,
    float* __restrict__ Cf, __half* __restrict__ Chh, __half* __restrict__ Chl,
    int mode, float scale) {
    extern __shared__ __half gsm[];
    const int tid = threadIdx.x;
    const int lane = tid & 31, wid = tid >> 5;
    const int gid = lane >> 2, tig = lane & 3;
    const int wm = (wid & 3) * 32, wn = (wid >> 2) * 64;
    const int bm = blockIdx.y * 128, bn = blockIdx.x * 256;

    auto load_stage = [&](int stage, int kt) {
        const int k0 = kt * 32;
        __half* sb = gsm + stage * GEMM_STAGE;
#pragma unroll
        for (int i = tid; i < 2048; i += 512) {
            int r = i >> 2, c = i & 3;
            const __half* src;
            if (r < 128)      src = Ah_ + (size_t)(bm + r) * DIM + k0 + c * 8;
            else if (r < 256) src = Al_ + (size_t)(bm + r - 128) * DIM + k0 + c * 8;
            else              src = B_  + (size_t)(bn + r - 256) * DIM + k0 + c * 8;
            cp16(sb + r * GP + c * 8, src);
        }
    };

    float acc[2][8][4];
#pragma unroll
    for (int mt = 0; mt < 2; mt++)
#pragma unroll
        for (int jn = 0; jn < 8; jn++)
#pragma unroll
            for (int e = 0; e < 4; e++) acc[mt][jn][e] = 0.f;

    load_stage(0, 0); CP_COMMIT();
    load_stage(1, 1); CP_COMMIT();

    for (int kt = 0; kt < GEMM_NKT; kt++) {
        if (kt + 2 < GEMM_NKT) load_stage((kt + 2) % 3, kt + 2);
        CP_COMMIT();
        CP_WAIT2();
        __syncthreads();

        const __half* st = gsm + (kt % 3) * GEMM_STAGE;
        const __half* As_h = st;
        const __half* As_l = st + 128 * GP;
        const __half* Bs   = st + 256 * GP;
#pragma unroll
        for (int kk = 0; kk < 2; kk++) {
            const int kc = kk * 16 + 2 * tig;
            unsigned ah[2][4], al[2][4];
#pragma unroll
            for (int mt = 0; mt < 2; mt++) {
                int row = wm + 16 * mt + gid;
                ah[mt][0] = *(const unsigned*)&As_h[row * GP + kc];
                ah[mt][1] = *(const unsigned*)&As_h[(row + 8) * GP + kc];
                ah[mt][2] = *(const unsigned*)&As_h[row * GP + kc + 8];
                ah[mt][3] = *(const unsigned*)&As_h[(row + 8) * GP + kc + 8];
                al[mt][0] = *(const unsigned*)&As_l[row * GP + kc];
                al[mt][1] = *(const unsigned*)&As_l[(row + 8) * GP + kc];
                al[mt][2] = *(const unsigned*)&As_l[row * GP + kc + 8];
                al[mt][3] = *(const unsigned*)&As_l[(row + 8) * GP + kc + 8];
            }
#pragma unroll
            for (int jn = 0; jn < 8; jn++) {
                int n = wn + 8 * jn + gid;
                unsigned b0 = *(const unsigned*)&Bs[n * GP + kc];
                unsigned b1 = *(const unsigned*)&Bs[n * GP + kc + 8];
#pragma unroll
                for (int mt = 0; mt < 2; mt++) {
                    mma16816h(acc[mt][jn], ah[mt], b0, b1);
                    mma16816h(acc[mt][jn], al[mt], b0, b1);
                }
            }
        }
        __syncthreads();
    }

#pragma unroll
    for (int mt = 0; mt < 2; mt++) {
        int row0 = bm + wm + 16 * mt + gid;
#pragma unroll
        for (int jn = 0; jn < 8; jn++) {
            int col = bn + wn + 8 * jn + 2 * tig;
            float x0 = acc[mt][jn][0] * scale, x1 = acc[mt][jn][1] * scale;
            float x2 = acc[mt][jn][2] * scale, x3 = acc[mt][jn][3] * scale;
            if (mode == 0) {
                *(float2*)&Cf[(size_t)row0 * DIM + col] = make_float2(x0, x1);
                *(float2*)&Cf[(size_t)(row0 + 8) * DIM + col] = make_float2(x2, x3);
            } else {
                *(unsigned*)&Chh[(size_t)row0 * DIM + col] =
                    pkh(__float2half_rn(x0), __float2half_rn(x1));
                *(unsigned*)&Chh[(size_t)(row0 + 8) * DIM + col] =
                    pkh(__float2half_rn(x2), __float2half_rn(x3));
            }
        }
    }
    (void)Chl;
}

// ---------------- flash attention: single fp16, 4-stage KV, 2 CTAs/SM --------
#define AP 72
#define ATTN_NKT (T_SEQ / 64)
#define KV_STAGE (2 * 64 * AP)
#define ATTN_SMEM ((128 * AP + 4 * KV_STAGE) * 2)    // 92160 B

__global__ __launch_bounds__(256, 2) void attn_mma(
    const __half* __restrict__ Q_, const __half* __restrict__ K_,
    const __half* __restrict__ Vt_, const float* __restrict__ mask,
    __half* __restrict__ Oh_, __half* __restrict__ Ol_) {
    extern __shared__ __half asm_[];
    __half* Qs = asm_;
    __half* KV = Qs + 128 * AP;

    const int tid = threadIdx.x;
    const int lane = tid & 31, wid = tid >> 5;
    const int gid = lane >> 2, tig = lane & 3;
    const int bq = blockIdx.x, h = blockIdx.y, b = blockIdx.z;
    const int bh = b * NH + h;
    const int qrow0 = b * T_SEQ + bq * 128;

    auto load_kv = [&](int stage, int kt) {
        const int krow0 = b * T_SEQ + kt * 64;
        __half* sb = KV + stage * KV_STAGE;
#pragma unroll
        for (int i = tid; i < 1024; i += 256) {
            int a = i >> 9, r = (i >> 3) & 63, c = i & 7;
            __half* dst = sb + a * 64 * AP + r * AP + c * 8;
            if (a == 0)
                cp16(dst, K_ + (size_t)(krow0 + r) * DIM + h * HS + c * 8);
            else
                cp16(dst, Vt_ + (size_t)(bh * HS + r) * T_SEQ + kt * 64 + c * 8);
        }
    };

#pragma unroll
    for (int i = tid; i < 128 * 8; i += 256) {
        int r = i >> 3, c8 = (i & 7) * 8;
        *(int4*)&Qs[r * AP + c8] =
            *(const int4*)&Q_[(size_t)(qrow0 + r) * DIM + h * HS + c8];
    }

    load_kv(0, 0); CP_COMMIT();
    load_kv(1, 1); CP_COMMIT();
    load_kv(2, 2); CP_COMMIT();

    float mi[2] = {-1e30f, -1e30f}, li[2] = {0.f, 0.f};
    float accO[8][4];
#pragma unroll
    for (int jn = 0; jn < 8; jn++)
#pragma unroll
        for (int e = 0; e < 4; e++) accO[jn][e] = 0.f;

    const int q0g = bq * 128 + 16 * wid + gid;
    const float* mrow = mask + (size_t)bh * T_SEQ * T_SEQ;
    __syncthreads();

    for (int kt = 0; kt < ATTN_NKT; kt++) {
        if (kt + 3 < ATTN_NKT) load_kv((kt + 3) & 3, kt + 3);
        CP_COMMIT();

        float2 mr0[8], mr1[8];
#pragma unroll
        for (int jn = 0; jn < 8; jn++) {
            int c = kt * 64 + 8 * jn + 2 * tig;
            mr0[jn] = *(const float2*)&mrow[(size_t)q0g * T_SEQ + c];
            mr1[jn] = *(const float2*)&mrow[(size_t)(q0g + 8) * T_SEQ + c];
        }

        CP_WAIT3();
        __syncthreads();
        const __half* K_s = KV + (kt & 3) * KV_STAGE;
        const __half* V_s = K_s + 64 * AP;

        float sc[8][4];
#pragma unroll
        for (int jn = 0; jn < 8; jn++)
#pragma unroll
            for (int e = 0; e < 4; e++) sc[jn][e] = 0.f;
#pragma unroll
        for (int kk = 0; kk < 4; kk++) {
            const int kc = kk * 16 + 2 * tig;
            const int row = 16 * wid + gid;
            unsigned qa[4];
            qa[0] = *(const unsigned*)&Qs[row * AP + kc];
            qa[1] = *(const unsigned*)&Qs[(row + 8) * AP + kc];
            qa[2] = *(const unsigned*)&Qs[row * AP + kc + 8];
            qa[3] = *(const unsigned*)&Qs[(row + 8) * AP + kc + 8];
#pragma unroll
            for (int jn = 0; jn < 8; jn++) {
                int n = 8 * jn + gid;
                unsigned kf0 = *(const unsigned*)&K_s[n * AP + kc];
                unsigned kf1 = *(const unsigned*)&K_s[n * AP + kc + 8];
                mma16816h(sc[jn], qa, kf0, kf1);
            }
        }

#pragma unroll
        for (int jn = 0; jn < 8; jn++) {
            sc[jn][0] = fmaf(mr0[jn].x, NEG_INF_F, sc[jn][0]);
            sc[jn][1] = fmaf(mr0[jn].y, NEG_INF_F, sc[jn][1]);
            sc[jn][2] = fmaf(mr1[jn].x, NEG_INF_F, sc[jn][2]);
            sc[jn][3] = fmaf(mr1[jn].y, NEG_INF_F, sc[jn][3]);
        }

        float mx0 = -1e30f, mx1 = -1e30f;
#pragma unroll
        for (int jn = 0; jn < 8; jn++) {
            mx0 = fmaxf(mx0, fmaxf(sc[jn][0], sc[jn][1]));
            mx1 = fmaxf(mx1, fmaxf(sc[jn][2], sc[jn][3]));
        }
        mx0 = fmaxf(mx0, __shfl_xor_sync(0xffffffffu, mx0, 1));
        mx0 = fmaxf(mx0, __shfl_xor_sync(0xffffffffu, mx0, 2));
        mx1 = fmaxf(mx1, __shfl_xor_sync(0xffffffffu, mx1, 1));
        mx1 = fmaxf(mx1, __shfl_xor_sync(0xffffffffu, mx1, 2));
        float mn0 = fmaxf(mi[0], mx0), mn1 = fmaxf(mi[1], mx1);
        float corr0 = __expf(mi[0] - mn0), corr1 = __expf(mi[1] - mn1);
        mi[0] = mn0; mi[1] = mn1;
        float rs0 = 0.f, rs1 = 0.f;
#pragma unroll
        for (int jn = 0; jn < 8; jn++) {
            sc[jn][0] = __expf(sc[jn][0] - mn0); rs0 += sc[jn][0];
            sc[jn][1] = __expf(sc[jn][1] - mn0); rs0 += sc[jn][1];
            sc[jn][2] = __expf(sc[jn][2] - mn1); rs1 += sc[jn][2];
            sc[jn][3] = __expf(sc[jn][3] - mn1); rs1 += sc[jn][3];
        }
        rs0 += __shfl_xor_sync(0xffffffffu, rs0, 1);
        rs0 += __shfl_xor_sync(0xffffffffu, rs0, 2);
        rs1 += __shfl_xor_sync(0xffffffffu, rs1, 1);
        rs1 += __shfl_xor_sync(0xffffffffu, rs1, 2);
        li[0] = li[0] * corr0 + rs0;
        li[1] = li[1] * corr1 + rs1;
#pragma unroll
        for (int jn = 0; jn < 8; jn++) {
            accO[jn][0] *= corr0; accO[jn][1] *= corr0;
            accO[jn][2] *= corr1; accO[jn][3] *= corr1;
        }

#pragma unroll
        for (int kk2 = 0; kk2 < 4; kk2++) {
            const int j0 = 2 * kk2, j1 = 2 * kk2 + 1;
            unsigned pa[4];
            pa[0] = pkh(__float2half_rn(sc[j0][0]), __float2half_rn(sc[j0][1]));
            pa[1] = pkh(__float2half_rn(sc[j0][2]), __float2half_rn(sc[j0][3]));
            pa[2] = pkh(__float2half_rn(sc[j1][0]), __float2half_rn(sc[j1][1]));
            pa[3] = pkh(__float2half_rn(sc[j1][2]), __float2half_rn(sc[j1][3]));
            const int kc = kk2 * 16 + 2 * tig;
#pragma unroll
            for (int jn = 0; jn < 8; jn++) {
                int n = 8 * jn + gid;
                unsigned vf0 = *(const unsigned*)&V_s[n * AP + kc];
                unsigned vf1 = *(const unsigned*)&V_s[n * AP + kc + 8];
                mma16816h(accO[jn], pa, vf0, vf1);
            }
        }
        __syncthreads();
    }

    const float inv0 = 1.f / li[0], inv1 = 1.f / li[1];
    const int row0 = qrow0 + 16 * wid + gid;
#pragma unroll
    for (int jn = 0; jn < 8; jn++) {
        int col = h * HS + 8 * jn + 2 * tig;
        unsigned ph, pl;
        split_pack2h(accO[jn][0] * inv0, accO[jn][1] * inv0, ph, pl);
        *(unsigned*)&Oh_[(size_t)row0 * DIM + col] = ph;
        *(unsigned*)&Ol_[(size_t)row0 * DIM + col] = pl;
        split_pack2h(accO[jn][2] * inv1, accO[jn][3] * inv1, ph, pl);
        *(unsigned*)&Oh_[(size_t)(row0 + 8) * DIM + col] = ph;
        *(unsigned*)&Ol_[(size_t)(row0 + 8) * DIM + col] = pl;
    }
}

// ---------------------------------------------------------------------------
extern "C" void kernel_launch(void* const* d_in, const int* in_sizes, int n_in,
                              void* d_out, int out_size) {
    const float* Xq   = (const float*)d_in[0];
    const float* Xr   = (const float*)d_in[1];
    const float* mask = (const float*)d_in[2];
    const float* Wq   = (const float*)d_in[3];
    const float* Wk   = (const float*)d_in[4];
    const float* Wv   = (const float*)d_in[5];
    const float* Wo   = (const float*)d_in[6];
    float* out = (float*)d_out;

    __half *Xqh, *Xql, *Xrh, *Xrl, *WqT, *WkT, *WvT, *WoT;
    __half *Q16, *K16, *V16, *Vt16, *O16h, *O16l;
    cudaGetSymbolAddress((void**)&Xqh, g_Xqh);   cudaGetSymbolAddress((void**)&Xql, g_Xql);
    cudaGetSymbolAddress((void**)&Xrh, g_Xrh);   cudaGetSymbolAddress((void**)&Xrl, g_Xrl);
    cudaGetSymbolAddress((void**)&WqT, g_WqT);   cudaGetSymbolAddress((void**)&WkT, g_WkT);
    cudaGetSymbolAddress((void**)&WvT, g_WvT);   cudaGetSymbolAddress((void**)&WoT, g_WoT);
    cudaGetSymbolAddress((void**)&Q16, g_Q16);   cudaGetSymbolAddress((void**)&K16, g_K16);
    cudaGetSymbolAddress((void**)&V16, g_V16);   cudaGetSymbolAddress((void**)&Vt16, g_Vt16);
    cudaGetSymbolAddress((void**)&O16h, g_O16h); cudaGetSymbolAddress((void**)&O16l, g_O16l);

    cudaFuncSetAttribute(attn_mma, cudaFuncAttributeMaxDynamicSharedMemorySize, ATTN_SMEM);
    cudaFuncSetAttribute(gemm_mma, cudaFuncAttributeMaxDynamicSharedMemorySize, GEMM_SMEM);

    dim3 gg(DIM / 256, NT_ROWS / 128);   // (4, 32) = 128 CTAs = one wave

    // launch order keeps gemm_mma(Q) at ncu index 5
    split_x_all<<<dim3(NELEM / 1024, 2), 256>>>(Xq, Xr, Xqh, Xql, Xrh, Xrl);      // 0
    split_wT_all<<<dim3(32, 32, 4), 256>>>(Wq, Wk, Wv, Wo, WqT, WkT, WvT, WoT);   // 1
    gemm_mma<<<gg, 512, GEMM_SMEM>>>(Xrh, Xrl, WkT, nullptr, K16, nullptr, 2, 1.0f);   // 2
    gemm_mma<<<gg, 512, GEMM_SMEM>>>(Xrh, Xrl, WvT, nullptr, V16, nullptr, 2, 1.0f);   // 3
    transpose_v<<<dim3(T_SEQ / 64, NB * NH), 256>>>(V16, Vt16);                         // 4
    gemm_mma<<<gg, 512, GEMM_SMEM>>>(Xqh, Xql, WqT, nullptr, Q16, nullptr, 2, 0.125f); // 5 <- ncu
    attn_mma<<<dim3(T_SEQ / 128, NH, NB), 256, ATTN_SMEM>>>(
        Q16, K16, Vt16, mask, O16h, O16l);                                              // 6
    gemm_mma<<<gg, 512, GEMM_SMEM>>>(O16h, O16l, WoT, out, nullptr, nullptr, 0, 1.0f); // 7
}

// round 10
// speedup vs baseline: 1.9649x; 1.2168x over previous
#include <cuda_runtime.h>
#include <cuda_fp16.h>
#include <cstdint>

#define T_SEQ 2048
#define NB 2
#define DIM 1024
#define NH 16
#define HS 64
#define NT_ROWS 4096
#define NEG_INF_F (-1e9f)
#define NELEM (NT_ROWS * DIM)

// ---------------- scratch (__device__ globals: allocation-free rule) --------
__device__ __half g_Xq16[NELEM];     // X single fp16
__device__ __half g_Xr16[NELEM];
__device__ __half g_WqT[DIM * DIM];  // W transposed, single fp16
__device__ __half g_WkT[DIM * DIM];
__device__ __half g_WvT[DIM * DIM];
__device__ __half g_WoT[DIM * DIM];
__device__ __half g_Q16[NELEM];
__device__ __half g_K16[NELEM];
__device__ __half g_V16[NELEM];
__device__ __half g_Vt16[NELEM];
__device__ __half g_O16[NELEM];

// ---------------- helpers ---------------------------------------------------
__device__ __forceinline__ unsigned pkh(__half a, __half b) {
    return (unsigned)__half_as_ushort(a) | ((unsigned)__half_as_ushort(b) << 16);
}
__device__ __forceinline__ void mma16816h(float (&d)[4], const unsigned (&a)[4],
                                          unsigned b0, unsigned b1) {
    asm volatile(
        "mma.sync.aligned.m16n8k16.row.col.f32.f16.f16.f32 "
        "{%0,%1,%2,%3}, {%4,%5,%6,%7}, {%8,%9}, {%0,%1,%2,%3};"
        : "+f"(d[0]), "+f"(d[1]), "+f"(d[2]), "+f"(d[3])
        : "r"(a[0]), "r"(a[1]), "r"(a[2]), "r"(a[3]), "r"(b0), "r"(b1));
}
__device__ __forceinline__ uint32_t smem_u32(const void* p) {
    uint32_t a;
    asm("{ .reg .u64 t; cvta.to.shared.u64 t, %1; cvt.u32.u64 %0, t; }" : "=r"(a) : "l"(p));
    return a;
}
__device__ __forceinline__ void cp16(void* smem_dst, const void* gsrc) {
    uint32_t s = smem_u32(smem_dst);
    asm volatile("cp.async.cg.shared.global [%0], [%1], 16;" :: "r"(s), "l"(gsrc) : "memory");
}
#define CP_COMMIT() asm volatile("cp.async.commit_group;" ::: "memory")
#define CP_WAIT2() asm volatile("cp.async.wait_group 2;" ::: "memory")
#define CP_WAIT3() asm volatile("cp.async.wait_group 3;" ::: "memory")

// ---------------- split kernels ----------------------------------------------
// z = 0: Xq ; z = 1: Xr  (single fp16 out)
__global__ __launch_bounds__(256) void split_x_all(
    const float* __restrict__ Xq, const float* __restrict__ Xr,
    __half* __restrict__ Xq16, __half* __restrict__ Xr16) {
    const int z = blockIdx.y;
    const float* X = z ? Xr : Xq;
    __half* Xo = z ? Xr16 : Xq16;
    size_t i = ((size_t)blockIdx.x * 256 + threadIdx.x) * 4;
    float4 v = *(const float4*)(X + i);
    *(unsigned*)&Xo[i]     = pkh(__float2half_rn(v.x), __float2half_rn(v.y));
    *(unsigned*)&Xo[i + 2] = pkh(__float2half_rn(v.z), __float2half_rn(v.w));
}

__global__ __launch_bounds__(256) void split_wT_all(
    const float* __restrict__ W0, const float* __restrict__ W1,
    const float* __restrict__ W2, const float* __restrict__ W3,
    __half* __restrict__ T0, __half* __restrict__ T1,
    __half* __restrict__ T2, __half* __restrict__ T3) {
    const int z = blockIdx.z;
    const float* W = (z == 0) ? W0 : (z == 1) ? W1 : (z == 2) ? W2 : W3;
    __half* Wt = (z == 0) ? T0 : (z == 1) ? T1 : (z == 2) ? T2 : T3;
    __shared__ float S[32][33];
    const int n0 = blockIdx.x * 32, k0 = blockIdx.y * 32;
    const int tid = threadIdx.x;
#pragma unroll
    for (int i = tid; i < 1024; i += 256) {
        int r = i >> 5, c = i & 31;
        S[r][c] = W[(size_t)(k0 + r) * DIM + n0 + c];
    }
    __syncthreads();
#pragma unroll
    for (int i = tid; i < 1024; i += 256) {
        int rr = i >> 5, cc = i & 31;
        Wt[(size_t)(n0 + rr) * DIM + k0 + cc] = __float2half_rn(S[cc][rr]);
    }
}

__global__ __launch_bounds__(256) void transpose_v(const __half* __restrict__ V,
                                                   __half* __restrict__ Vt) {
    __shared__ __half S[64][66];
    const int tt = blockIdx.x, bh = blockIdx.y;
    const int b = bh >> 4, h = bh & 15;
    const int tid = threadIdx.x;
#pragma unroll
    for (int i = tid; i < 64 * 32; i += 256) {
        int r = i >> 5, c2 = (i & 31) * 2;
        size_t g = (size_t)(b * T_SEQ + tt * 64 + r) * DIM + h * HS + c2;
        *(unsigned*)&S[r][c2] = *(const unsigned*)&V[g];
    }
    __syncthreads();
#pragma unroll
    for (int i = tid; i < 64 * 32; i += 256) {
        int s = i >> 5, t2 = (i & 31) * 2;
        size_t g = (size_t)(bh * HS + s) * T_SEQ + tt * 64 + t2;
        *(unsigned*)&Vt[g] = pkh(S[t2][s], S[t2 + 1][s]);
    }
}

// ---------------- single-fp16 GEMM: 128x256x32 tile, 512 thr, 3-stage --------
// C = scale * (A @ B); A fp16 [m][k], Bt fp16 [n][k].
// modes: 0 fp32 out; 2 fp16 out. Grid (4, 32) = 128 CTAs = one wave.
#define GP 40
#define GEMM_NKT 32
#define GEMM_STAGE (384 * GP)               // A 128 rows + B 256 rows
#define GEMM_SMEM (3 * GEMM_STAGE * 2)      // 92160 B

__global__ __launch_bounds__(512, 1) void gemm_mma(
    const __half* __restrict__ A_, const __half* __restrict__ B_,
    float* __restrict__ Cf, __half* __restrict__ Ch, int mode, float scale) {
    extern __shared__ __half gsm[];
    const int tid = threadIdx.x;
    const int lane = tid & 31, wid = tid >> 5;
    const int gid = lane >> 2, tig = lane & 3;
    const int wm = (wid & 3) * 32, wn = (wid >> 2) * 64;
    const int bm = blockIdx.y * 128, bn = blockIdx.x * 256;

    auto load_stage = [&](int stage, int kt) {
        const int k0 = kt * 32;
        __half* sb = gsm + stage * GEMM_STAGE;
#pragma unroll
        for (int i = tid; i < 1536; i += 512) {
            int r = i >> 2, c = i & 3;
            const __half* src = (r < 128)
                ? A_ + (size_t)(bm + r) * DIM + k0 + c * 8
                : B_ + (size_t)(bn + r - 128) * DIM + k0 + c * 8;
            cp16(sb + r * GP + c * 8, src);
        }
    };

    float acc[2][8][4];
#pragma unroll
    for (int mt = 0; mt < 2; mt++)
#pragma unroll
        for (int jn = 0; jn < 8; jn++)
#pragma unroll
            for (int e = 0; e < 4; e++) acc[mt][jn][e] = 0.f;

    load_stage(0, 0); CP_COMMIT();
    load_stage(1, 1); CP_COMMIT();

    for (int kt = 0; kt < GEMM_NKT; kt++) {
        if (kt + 2 < GEMM_NKT) load_stage((kt + 2) % 3, kt + 2);
        CP_COMMIT();
        CP_WAIT2();
        __syncthreads();

        const __half* st = gsm + (kt % 3) * GEMM_STAGE;
        const __half* As = st;
        const __half* Bs = st + 128 * GP;
#pragma unroll
        for (int kk = 0; kk < 2; kk++) {
            const int kc = kk * 16 + 2 * tig;
            unsigned af[2][4];
#pragma unroll
            for (int mt = 0; mt < 2; mt++) {
                int row = wm + 16 * mt + gid;
                af[mt][0] = *(const unsigned*)&As[row * GP + kc];
                af[mt][1] = *(const unsigned*)&As[(row + 8) * GP + kc];
                af[mt][2] = *(const unsigned*)&As[row * GP + kc + 8];
                af[mt][3] = *(const unsigned*)&As[(row + 8) * GP + kc + 8];
            }
#pragma unroll
            for (int jn = 0; jn < 8; jn++) {
                int n = wn + 8 * jn + gid;
                unsigned b0 = *(const unsigned*)&Bs[n * GP + kc];
                unsigned b1 = *(const unsigned*)&Bs[n * GP + kc + 8];
#pragma unroll
                for (int mt = 0; mt < 2; mt++)
                    mma16816h(acc[mt][jn], af[mt], b0, b1);
            }
        }
        __syncthreads();
    }

#pragma unroll
    for (int mt = 0; mt < 2; mt++) {
        int row0 = bm + wm + 16 * mt + gid;
#pragma unroll
        for (int jn = 0; jn < 8; jn++) {
            int col = bn + wn + 8 * jn + 2 * tig;
            float x0 = acc[mt][jn][0] * scale, x1 = acc[mt][jn][1] * scale;
            float x2 = acc[mt][jn][2] * scale, x3 = acc[mt][jn][3] * scale;
            if (mode == 0) {
                *(float2*)&Cf[(size_t)row0 * DIM + col] = make_float2(x0, x1);
                *(float2*)&Cf[(size_t)(row0 + 8) * DIM + col] = make_float2(x2, x3);
            } else {
                *(unsigned*)&Ch[(size_t)row0 * DIM + col] =
                    pkh(__float2half_rn(x0), __float2half_rn(x1));
                *(unsigned*)&Ch[(size_t)(row0 + 8) * DIM + col] =
                    pkh(__float2half_rn(x2), __float2half_rn(x3));
            }
        }
    }
}

// ---------------- flash attention: single fp16, 4-stage KV, 2 CTAs/SM --------
#define AP 72
#define ATTN_NKT (T_SEQ / 64)
#define KV_STAGE (2 * 64 * AP)
#define ATTN_SMEM ((128 * AP + 4 * KV_STAGE) * 2)    // 92160 B

__global__ __launch_bounds__(256, 2) void attn_mma(
    const __half* __restrict__ Q_, const __half* __restrict__ K_,
    const __half* __restrict__ Vt_, const float* __restrict__ mask,
    __half* __restrict__ O_) {
    extern __shared__ __half asm_[];
    __half* Qs = asm_;
    __half* KV = Qs + 128 * AP;

    const int tid = threadIdx.x;
    const int lane = tid & 31, wid = tid >> 5;
    const int gid = lane >> 2, tig = lane & 3;
    const int bq = blockIdx.x, h = blockIdx.y, b = blockIdx.z;
    const int bh = b * NH + h;
    const int qrow0 = b * T_SEQ + bq * 128;

    auto load_kv = [&](int stage, int kt) {
        const int krow0 = b * T_SEQ + kt * 64;
        __half* sb = KV + stage * KV_STAGE;
#pragma unroll
        for (int i = tid; i < 1024; i += 256) {
            int a = i >> 9, r = (i >> 3) & 63, c = i & 7;
            __half* dst = sb + a * 64 * AP + r * AP + c * 8;
            if (a == 0)
                cp16(dst, K_ + (size_t)(krow0 + r) * DIM + h * HS + c * 8);
            else
                cp16(dst, Vt_ + (size_t)(bh * HS + r) * T_SEQ + kt * 64 + c * 8);
        }
    };

#pragma unroll
    for (int i = tid; i < 128 * 8; i += 256) {
        int r = i >> 3, c8 = (i & 7) * 8;
        *(int4*)&Qs[r * AP + c8] =
            *(const int4*)&Q_[(size_t)(qrow0 + r) * DIM + h * HS + c8];
    }

    load_kv(0, 0); CP_COMMIT();
    load_kv(1, 1); CP_COMMIT();
    load_kv(2, 2); CP_COMMIT();

    float mi[2] = {-1e30f, -1e30f}, li[2] = {0.f, 0.f};
    float accO[8][4];
#pragma unroll
    for (int jn = 0; jn < 8; jn++)
#pragma unroll
        for (int e = 0; e < 4; e++) accO[jn][e] = 0.f;

    const int q0g = bq * 128 + 16 * wid + gid;
    const float* mrow = mask + (size_t)bh * T_SEQ * T_SEQ;
    __syncthreads();

    for (int kt = 0; kt < ATTN_NKT; kt++) {
        if (kt + 3 < ATTN_NKT) load_kv((kt + 3) & 3, kt + 3);
        CP_COMMIT();

        float2 mr0[8], mr1[8];
#pragma unroll
        for (int jn = 0; jn < 8; jn++) {
            int c = kt * 64 + 8 * jn + 2 * tig;
            mr0[jn] = *(const float2*)&mrow[(size_t)q0g * T_SEQ + c];
            mr1[jn] = *(const float2*)&mrow[(size_t)(q0g + 8) * T_SEQ + c];
        }

        CP_WAIT3();
        __syncthreads();
        const __half* K_s = KV + (kt & 3) * KV_STAGE;
        const __half* V_s = K_s + 64 * AP;

        float sc[8][4];
#pragma unroll
        for (int jn = 0; jn < 8; jn++)
#pragma unroll
            for (int e = 0; e < 4; e++) sc[jn][e] = 0.f;
#pragma unroll
        for (int kk = 0; kk < 4; kk++) {
            const int kc = kk * 16 + 2 * tig;
            const int row = 16 * wid + gid;
            unsigned qa[4];
            qa[0] = *(const unsigned*)&Qs[row * AP + kc];
            qa[1] = *(const unsigned*)&Qs[(row + 8) * AP + kc];
            qa[2] = *(const unsigned*)&Qs[row * AP + kc + 8];
            qa[3] = *(const unsigned*)&Qs[(row + 8) * AP + kc + 8];
#pragma unroll
            for (int jn = 0; jn < 8; jn++) {
                int n = 8 * jn + gid;
                unsigned kf0 = *(const unsigned*)&K_s[n * AP + kc];
                unsigned kf1 = *(const unsigned*)&K_s[n * AP + kc + 8];
                mma16816h(sc[jn], qa, kf0, kf1);
            }
        }

#pragma unroll
        for (int jn = 0; jn < 8; jn++) {
            sc[jn][0] = fmaf(mr0[jn].x, NEG_INF_F, sc[jn][0]);
            sc[jn][1] = fmaf(mr0[jn].y, NEG_INF_F, sc[jn][1]);
            sc[jn][2] = fmaf(mr1[jn].x, NEG_INF_F, sc[jn][2]);
            sc[jn][3] = fmaf(mr1[jn].y, NEG_INF_F, sc[jn][3]);
        }

        float mx0 = -1e30f, mx1 = -1e30f;
#pragma unroll
        for (int jn = 0; jn < 8; jn++) {
            mx0 = fmaxf(mx0, fmaxf(sc[jn][0], sc[jn][1]));
            mx1 = fmaxf(mx1, fmaxf(sc[jn][2], sc[jn][3]));
        }
        mx0 = fmaxf(mx0, __shfl_xor_sync(0xffffffffu, mx0, 1));
        mx0 = fmaxf(mx0, __shfl_xor_sync(0xffffffffu, mx0, 2));
        mx1 = fmaxf(mx1, __shfl_xor_sync(0xffffffffu, mx1, 1));
        mx1 = fmaxf(mx1, __shfl_xor_sync(0xffffffffu, mx1, 2));
        float mn0 = fmaxf(mi[0], mx0), mn1 = fmaxf(mi[1], mx1);
        float corr0 = __expf(mi[0] - mn0), corr1 = __expf(mi[1] - mn1);
        mi[0] = mn0; mi[1] = mn1;
        float rs0 = 0.f, rs1 = 0.f;
#pragma unroll
        for (int jn = 0; jn < 8; jn++) {
            sc[jn][0] = __expf(sc[jn][0] - mn0); rs0 += sc[jn][0];
            sc[jn][1] = __expf(sc[jn][1] - mn0); rs0 += sc[jn][1];
            sc[jn][2] = __expf(sc[jn][2] - mn1); rs1 += sc[jn][2];
            sc[jn][3] = __expf(sc[jn][3] - mn1); rs1 += sc[jn][3];
        }
        rs0 += __shfl_xor_sync(0xffffffffu, rs0, 1);
        rs0 += __shfl_xor_sync(0xffffffffu, rs0, 2);
        rs1 += __shfl_xor_sync(0xffffffffu, rs1, 1);
        rs1 += __shfl_xor_sync(0xffffffffu, rs1, 2);
        li[0] = li[0] * corr0 + rs0;
        li[1] = li[1] * corr1 + rs1;
#pragma unroll
        for (int jn = 0; jn < 8; jn++) {
            accO[jn][0] *= corr0; accO[jn][1] *= corr0;
            accO[jn][2] *= corr1; accO[jn][3] *= corr1;
        }

#pragma unroll
        for (int kk2 = 0; kk2 < 4; kk2++) {
            const int j0 = 2 * kk2, j1 = 2 * kk2 + 1;
            unsigned pa[4];
            pa[0] = pkh(__float2half_rn(sc[j0][0]), __float2half_rn(sc[j0][1]));
            pa[1] = pkh(__float2half_rn(sc[j0][2]), __float2half_rn(sc[j0][3]));
            pa[2] = pkh(__float2half_rn(sc[j1][0]), __float2half_rn(sc[j1][1]));
            pa[3] = pkh(__float2half_rn(sc[j1][2]), __float2half_rn(sc[j1][3]));
            const int kc = kk2 * 16 + 2 * tig;
#pragma unroll
            for (int jn = 0; jn < 8; jn++) {
                int n = 8 * jn + gid;
                unsigned vf0 = *(const unsigned*)&V_s[n * AP + kc];
                unsigned vf1 = *(const unsigned*)&V_s[n * AP + kc + 8];
                mma16816h(accO[jn], pa, vf0, vf1);
            }
        }
        __syncthreads();
    }

    // ---- epilogue: normalize, single fp16 O ----
    const float inv0 = 1.f / li[0], inv1 = 1.f / li[1];
    const int row0 = qrow0 + 16 * wid + gid;
#pragma unroll
    for (int jn = 0; jn < 8; jn++) {
        int col = h * HS + 8 * jn + 2 * tig;
        *(unsigned*)&O_[(size_t)row0 * DIM + col] =
            pkh(__float2half_rn(accO[jn][0] * inv0),
                __float2half_rn(accO[jn][1] * inv0));
        *(unsigned*)&O_[(size_t)(row0 + 8) * DIM + col] =
            pkh(__float2half_rn(accO[jn][2] * inv1),
                __float2half_rn(accO[jn][3] * inv1));
    }
}

// ---------------------------------------------------------------------------
extern "C" void kernel_launch(void* const* d_in, const int* in_sizes, int n_in,
                              void* d_out, int out_size) {
    const float* Xq   = (const float*)d_in[0];
    const float* Xr   = (const float*)d_in[1];
    const float* mask = (const float*)d_in[2];
    const float* Wq   = (const float*)d_in[3];
    const float* Wk   = (const float*)d_in[4];
    const float* Wv   = (const float*)d_in[5];
    const float* Wo   = (const float*)d_in[6];
    float* out = (float*)d_out;

    __half *Xq16, *Xr16, *WqT, *WkT, *WvT, *WoT;
    __half *Q16, *K16, *V16, *Vt16, *O16;
    cudaGetSymbolAddress((void**)&Xq16, g_Xq16); cudaGetSymbolAddress((void**)&Xr16, g_Xr16);
    cudaGetSymbolAddress((void**)&WqT, g_WqT);   cudaGetSymbolAddress((void**)&WkT, g_WkT);
    cudaGetSymbolAddress((void**)&WvT, g_WvT);   cudaGetSymbolAddress((void**)&WoT, g_WoT);
    cudaGetSymbolAddress((void**)&Q16, g_Q16);   cudaGetSymbolAddress((void**)&K16, g_K16);
    cudaGetSymbolAddress((void**)&V16, g_V16);   cudaGetSymbolAddress((void**)&Vt16, g_Vt16);
    cudaGetSymbolAddress((void**)&O16, g_O16);

    cudaFuncSetAttribute(attn_mma, cudaFuncAttributeMaxDynamicSharedMemorySize, ATTN_SMEM);
    cudaFuncSetAttribute(gemm_mma, cudaFuncAttributeMaxDynamicSharedMemorySize, GEMM_SMEM);

    dim3 gg(DIM / 256, NT_ROWS / 128);   // (4, 32) = 128 CTAs = one wave

    // launch order keeps gemm_mma(Q) at ncu index 5
    split_x_all<<<dim3(NELEM / 1024, 2), 256>>>(Xq, Xr, Xq16, Xr16);              // 0
    split_wT_all<<<dim3(32, 32, 4), 256>>>(Wq, Wk, Wv, Wo, WqT, WkT, WvT, WoT);   // 1
    gemm_mma<<<gg, 512, GEMM_SMEM>>>(Xr16, WkT, nullptr, K16, 2, 1.0f);           // 2
    gemm_mma<<<gg, 512, GEMM_SMEM>>>(Xr16, WvT, nullptr, V16, 2, 1.0f);           // 3
    transpose_v<<<dim3(T_SEQ / 64, NB * NH), 256>>>(V16, Vt16);                   // 4
    gemm_mma<<<gg, 512, GEMM_SMEM>>>(Xq16, WqT, nullptr, Q16, 2, 0.125f);         // 5 <- ncu
    attn_mma<<<dim3(T_SEQ / 128, NH, NB), 256, ATTN_SMEM>>>(
        Q16, K16, Vt16, mask, O16);                                               // 6
    gemm_mma<<<gg, 512, GEMM_SMEM>>>(O16, WoT, out, nullptr, 0, 1.0f);            // 7
}

// round 11
// speedup vs baseline: 2.1389x; 1.0886x over previous
#include <cuda_runtime.h>
#include <cuda_fp16.h>
#include <cstdint>

#define T_SEQ 2048
#define NB 2
#define DIM 1024
#define NH 16
#define HS 64
#define NT_ROWS 4096
#define NEG_INF_F (-1e9f)
#define NELEM (NT_ROWS * DIM)

// ---------------- scratch (__device__ globals: allocation-free rule) --------
__device__ __half g_Xq16[NELEM];
__device__ __half g_Xr16[NELEM];
__device__ __half g_WqT[DIM * DIM];
__device__ __half g_WkT[DIM * DIM];
__device__ __half g_WvT[DIM * DIM];
__device__ __half g_WoT[DIM * DIM];
__device__ __half g_Q16[NELEM];
__device__ __half g_K16[NELEM];
__device__ __half g_V16[NELEM];
__device__ __half g_Vt16[NELEM];
__device__ __half g_O16[NELEM];

// ---------------- helpers ---------------------------------------------------
__device__ __forceinline__ unsigned pkh(__half a, __half b) {
    return (unsigned)__half_as_ushort(a) | ((unsigned)__half_as_ushort(b) << 16);
}
__device__ __forceinline__ void mma16816h(float (&d)[4], const unsigned (&a)[4],
                                          unsigned b0, unsigned b1) {
    asm volatile(
        "mma.sync.aligned.m16n8k16.row.col.f32.f16.f16.f32 "
        "{%0,%1,%2,%3}, {%4,%5,%6,%7}, {%8,%9}, {%0,%1,%2,%3};"
        : "+f"(d[0]), "+f"(d[1]), "+f"(d[2]), "+f"(d[3])
        : "r"(a[0]), "r"(a[1]), "r"(a[2]), "r"(a[3]), "r"(b0), "r"(b1));
}
__device__ __forceinline__ uint32_t smem_u32(const void* p) {
    uint32_t a;
    asm("{ .reg .u64 t; cvta.to.shared.u64 t, %1; cvt.u32.u64 %0, t; }" : "=r"(a) : "l"(p));
    return a;
}
__device__ __forceinline__ void cp16(void* smem_dst, const void* gsrc) {
    uint32_t s = smem_u32(smem_dst);
    asm volatile("cp.async.cg.shared.global [%0], [%1], 16;" :: "r"(s), "l"(gsrc) : "memory");
}
#define CP_COMMIT() asm volatile("cp.async.commit_group;" ::: "memory")
#define CP_WAIT2() asm volatile("cp.async.wait_group 2;" ::: "memory")
#define CP_WAIT3() asm volatile("cp.async.wait_group 3;" ::: "memory")

// ---------------- split kernels ----------------------------------------------
__global__ __launch_bounds__(256) void split_x_all(
    const float* __restrict__ Xq, const float* __restrict__ Xr,
    __half* __restrict__ Xq16, __half* __restrict__ Xr16) {
    const int z = blockIdx.y;
    const float* X = z ? Xr : Xq;
    __half* Xo = z ? Xr16 : Xq16;
    size_t i = ((size_t)blockIdx.x * 256 + threadIdx.x) * 4;
    float4 v = *(const float4*)(X + i);
    *(unsigned*)&Xo[i]     = pkh(__float2half_rn(v.x), __float2half_rn(v.y));
    *(unsigned*)&Xo[i + 2] = pkh(__float2half_rn(v.z), __float2half_rn(v.w));
}

__global__ __launch_bounds__(256) void split_wT_all(
    const float* __restrict__ W0, const float* __restrict__ W1,
    const float* __restrict__ W2, const float* __restrict__ W3,
    __half* __restrict__ T0, __half* __restrict__ T1,
    __half* __restrict__ T2, __half* __restrict__ T3) {
    const int z = blockIdx.z;
    const float* W = (z == 0) ? W0 : (z == 1) ? W1 : (z == 2) ? W2 : W3;
    __half* Wt = (z == 0) ? T0 : (z == 1) ? T1 : (z == 2) ? T2 : T3;
    __shared__ float S[32][33];
    const int n0 = blockIdx.x * 32, k0 = blockIdx.y * 32;
    const int tid = threadIdx.x;
#pragma unroll
    for (int i = tid; i < 1024; i += 256) {
        int r = i >> 5, c = i & 31;
        S[r][c] = W[(size_t)(k0 + r) * DIM + n0 + c];
    }
    __syncthreads();
#pragma unroll
    for (int i = tid; i < 1024; i += 256) {
        int rr = i >> 5, cc = i & 31;
        Wt[(size_t)(n0 + rr) * DIM + k0 + cc] = __float2half_rn(S[cc][rr]);
    }
}

__global__ __launch_bounds__(256) void transpose_v(const __half* __restrict__ V,
                                                   __half* __restrict__ Vt) {
    __shared__ __half S[64][66];
    const int tt = blockIdx.x, bh = blockIdx.y;
    const int b = bh >> 4, h = bh & 15;
    const int tid = threadIdx.x;
#pragma unroll
    for (int i = tid; i < 64 * 32; i += 256) {
        int r = i >> 5, c2 = (i & 31) * 2;
        size_t g = (size_t)(b * T_SEQ + tt * 64 + r) * DIM + h * HS + c2;
        *(unsigned*)&S[r][c2] = *(const unsigned*)&V[g];
    }
    __syncthreads();
#pragma unroll
    for (int i = tid; i < 64 * 32; i += 256) {
        int s = i >> 5, t2 = (i & 31) * 2;
        size_t g = (size_t)(bh * HS + s) * T_SEQ + tt * 64 + t2;
        *(unsigned*)&Vt[g] = pkh(S[t2][s], S[t2 + 1][s]);
    }
}

// ---------------- single-fp16 GEMM core (shared by both launchers) -----------
#define GP 40
#define GEMM_NKT 32
#define GEMM_STAGE (384 * GP)
#define GEMM_SMEM (3 * GEMM_STAGE * 2)      // 92160 B

__device__ __forceinline__ void gemm_body(
    const __half* __restrict__ A_, const __half* __restrict__ B_,
    float* __restrict__ Cf, __half* __restrict__ Ch, int mode, float scale,
    __half* gsm, int bm, int bn) {
    const int tid = threadIdx.x;
    const int lane = tid & 31, wid = tid >> 5;
    const int gid = lane >> 2, tig = lane & 3;
    const int wm = (wid & 3) * 32, wn = (wid >> 2) * 64;

    auto load_stage = [&](int stage, int kt) {
        const int k0 = kt * 32;
        __half* sb = gsm + stage * GEMM_STAGE;
#pragma unroll
        for (int i = tid; i < 1536; i += 512) {
            int r = i >> 2, c = i & 3;
            const __half* src = (r < 128)
                ? A_ + (size_t)(bm + r) * DIM + k0 + c * 8
                : B_ + (size_t)(bn + r - 128) * DIM + k0 + c * 8;
            cp16(sb + r * GP + c * 8, src);
        }
    };

    float acc[2][8][4];
#pragma unroll
    for (int mt = 0; mt < 2; mt++)
#pragma unroll
        for (int jn = 0; jn < 8; jn++)
#pragma unroll
            for (int e = 0; e < 4; e++) acc[mt][jn][e] = 0.f;

    load_stage(0, 0); CP_COMMIT();
    load_stage(1, 1); CP_COMMIT();

    for (int kt = 0; kt < GEMM_NKT; kt++) {
        if (kt + 2 < GEMM_NKT) load_stage((kt + 2) % 3, kt + 2);
        CP_COMMIT();
        CP_WAIT2();
        __syncthreads();

        const __half* st = gsm + (kt % 3) * GEMM_STAGE;
        const __half* As = st;
        const __half* Bs = st + 128 * GP;
#pragma unroll
        for (int kk = 0; kk < 2; kk++) {
            const int kc = kk * 16 + 2 * tig;
            unsigned af[2][4];
#pragma unroll
            for (int mt = 0; mt < 2; mt++) {
                int row = wm + 16 * mt + gid;
                af[mt][0] = *(const unsigned*)&As[row * GP + kc];
                af[mt][1] = *(const unsigned*)&As[(row + 8) * GP + kc];
                af[mt][2] = *(const unsigned*)&As[row * GP + kc + 8];
                af[mt][3] = *(const unsigned*)&As[(row + 8) * GP + kc + 8];
            }
#pragma unroll
            for (int jn = 0; jn < 8; jn++) {
                int n = wn + 8 * jn + gid;
                unsigned b0 = *(const unsigned*)&Bs[n * GP + kc];
                unsigned b1 = *(const unsigned*)&Bs[n * GP + kc + 8];
#pragma unroll
                for (int mt = 0; mt < 2; mt++)
                    mma16816h(acc[mt][jn], af[mt], b0, b1);
            }
        }
        __syncthreads();
    }

#pragma unroll
    for (int mt = 0; mt < 2; mt++) {
        int row0 = bm + wm + 16 * mt + gid;
#pragma unroll
        for (int jn = 0; jn < 8; jn++) {
            int col = bn + wn + 8 * jn + 2 * tig;
            float x0 = acc[mt][jn][0] * scale, x1 = acc[mt][jn][1] * scale;
            float x2 = acc[mt][jn][2] * scale, x3 = acc[mt][jn][3] * scale;
            if (mode == 0) {
                *(float2*)&Cf[(size_t)row0 * DIM + col] = make_float2(x0, x1);
                *(float2*)&Cf[(size_t)(row0 + 8) * DIM + col] = make_float2(x2, x3);
            } else {
                *(unsigned*)&Ch[(size_t)row0 * DIM + col] =
                    pkh(__float2half_rn(x0), __float2half_rn(x1));
                *(unsigned*)&Ch[(size_t)(row0 + 8) * DIM + col] =
                    pkh(__float2half_rn(x2), __float2half_rn(x3));
            }
        }
    }
}

__global__ __launch_bounds__(512, 1) void gemm_mma(
    const __half* __restrict__ A_, const __half* __restrict__ B_,
    float* __restrict__ Cf, __half* __restrict__ Ch, int mode, float scale) {
    extern __shared__ __half gsm[];
    gemm_body(A_, B_, Cf, Ch, mode, scale, gsm,
              blockIdx.y * 128, blockIdx.x * 256);
}

// merged K/V projection: z = 0 -> K = Xr@Wk ; z = 1 -> V = Xr@Wv
__global__ __launch_bounds__(512, 1) void gemm_kv(
    const __half* __restrict__ Xr_, const __half* __restrict__ WkT_,
    const __half* __restrict__ WvT_, __half* __restrict__ K_,
    __half* __restrict__ V_) {
    extern __shared__ __half gsm2[];
    const int z = blockIdx.z;
    gemm_body(Xr_, z ? WvT_ : WkT_, nullptr, z ? V_ : K_, 2, 1.0f, gsm2,
              blockIdx.y * 128, blockIdx.x * 256);
}

// ---------------- flash attention: single fp16, max-free softmax -------------
#define AP 72
#define ATTN_NKT (T_SEQ / 64)
#define KV_STAGE (2 * 64 * AP)
#define ATTN_SMEM ((128 * AP + 4 * KV_STAGE) * 2)    // 92160 B

__global__ __launch_bounds__(256, 2) void attn_mma(
    const __half* __restrict__ Q_, const __half* __restrict__ K_,
    const __half* __restrict__ Vt_, const float* __restrict__ mask,
    __half* __restrict__ O_) {
    extern __shared__ __half asm_[];
    __half* Qs = asm_;
    __half* KV = Qs + 128 * AP;

    const int tid = threadIdx.x;
    const int lane = tid & 31, wid = tid >> 5;
    const int gid = lane >> 2, tig = lane & 3;
    const int bq = blockIdx.x, h = blockIdx.y, b = blockIdx.z;
    const int bh = b * NH + h;
    const int qrow0 = b * T_SEQ + bq * 128;

    auto load_kv = [&](int stage, int kt) {
        const int krow0 = b * T_SEQ + kt * 64;
        __half* sb = KV + stage * KV_STAGE;
#pragma unroll
        for (int i = tid; i < 1024; i += 256) {
            int a = i >> 9, r = (i >> 3) & 63, c = i & 7;
            __half* dst = sb + a * 64 * AP + r * AP + c * 8;
            if (a == 0)
                cp16(dst, K_ + (size_t)(krow0 + r) * DIM + h * HS + c * 8);
            else
                cp16(dst, Vt_ + (size_t)(bh * HS + r) * T_SEQ + kt * 64 + c * 8);
        }
    };

#pragma unroll
    for (int i = tid; i < 128 * 8; i += 256) {
        int r = i >> 3, c8 = (i & 7) * 8;
        *(int4*)&Qs[r * AP + c8] =
            *(const int4*)&Q_[(size_t)(qrow0 + r) * DIM + h * HS + c8];
    }

    load_kv(0, 0); CP_COMMIT();
    load_kv(1, 1); CP_COMMIT();
    load_kv(2, 2); CP_COMMIT();

    // max-free online softmax: only running denominators needed.
    float li[2] = {0.f, 0.f};
    float accO[8][4];
#pragma unroll
    for (int jn = 0; jn < 8; jn++)
#pragma unroll
        for (int e = 0; e < 4; e++) accO[jn][e] = 0.f;

    const int q0g = bq * 128 + 16 * wid + gid;
    const float* mrow = mask + (size_t)bh * T_SEQ * T_SEQ;
    __syncthreads();

    for (int kt = 0; kt < ATTN_NKT; kt++) {
        if (kt + 3 < ATTN_NKT) load_kv((kt + 3) & 3, kt + 3);
        CP_COMMIT();

        float2 mr0[8], mr1[8];
#pragma unroll
        for (int jn = 0; jn < 8; jn++) {
            int c = kt * 64 + 8 * jn + 2 * tig;
            mr0[jn] = *(const float2*)&mrow[(size_t)q0g * T_SEQ + c];
            mr1[jn] = *(const float2*)&mrow[(size_t)(q0g + 8) * T_SEQ + c];
        }

        CP_WAIT3();
        __syncthreads();
        const __half* K_s = KV + (kt & 3) * KV_STAGE;
        const __half* V_s = K_s + 64 * AP;

        float sc[8][4];
#pragma unroll
        for (int jn = 0; jn < 8; jn++)
#pragma unroll
            for (int e = 0; e < 4; e++) sc[jn][e] = 0.f;
#pragma unroll
        for (int kk = 0; kk < 4; kk++) {
            const int kc = kk * 16 + 2 * tig;
            const int row = 16 * wid + gid;
            unsigned qa[4];
            qa[0] = *(const unsigned*)&Qs[row * AP + kc];
            qa[1] = *(const unsigned*)&Qs[(row + 8) * AP + kc];
            qa[2] = *(const unsigned*)&Qs[row * AP + kc + 8];
            qa[3] = *(const unsigned*)&Qs[(row + 8) * AP + kc + 8];
#pragma unroll
            for (int jn = 0; jn < 8; jn++) {
                int n = 8 * jn + gid;
                unsigned kf0 = *(const unsigned*)&K_s[n * AP + kc];
                unsigned kf1 = *(const unsigned*)&K_s[n * AP + kc + 8];
                mma16816h(sc[jn], qa, kf0, kf1);
            }
        }

        // mask + exp (no max subtraction: scores are O(1); masked -> exp -> 0)
        float rs0 = 0.f, rs1 = 0.f;
#pragma unroll
        for (int jn = 0; jn < 8; jn++) {
            sc[jn][0] = __expf(fmaf(mr0[jn].x, NEG_INF_F, sc[jn][0])); rs0 += sc[jn][0];
            sc[jn][1] = __expf(fmaf(mr0[jn].y, NEG_INF_F, sc[jn][1])); rs0 += sc[jn][1];
            sc[jn][2] = __expf(fmaf(mr1[jn].x, NEG_INF_F, sc[jn][2])); rs1 += sc[jn][2];
            sc[jn][3] = __expf(fmaf(mr1[jn].y, NEG_INF_F, sc[jn][3])); rs1 += sc[jn][3];
        }
        rs0 += __shfl_xor_sync(0xffffffffu, rs0, 1);
        rs0 += __shfl_xor_sync(0xffffffffu, rs0, 2);
        rs1 += __shfl_xor_sync(0xffffffffu, rs1, 1);
        rs1 += __shfl_xor_sync(0xffffffffu, rs1, 2);
        li[0] += rs0;
        li[1] += rs1;

        // accO += P @ V
#pragma unroll
        for (int kk2 = 0; kk2 < 4; kk2++) {
            const int j0 = 2 * kk2, j1 = 2 * kk2 + 1;
            unsigned pa[4];
            pa[0] = pkh(__float2half_rn(sc[j0][0]), __float2half_rn(sc[j0][1]));
            pa[1] = pkh(__float2half_rn(sc[j0][2]), __float2half_rn(sc[j0][3]));
            pa[2] = pkh(__float2half_rn(sc[j1][0]), __float2half_rn(sc[j1][1]));
            pa[3] = pkh(__float2half_rn(sc[j1][2]), __float2half_rn(sc[j1][3]));
            const int kc = kk2 * 16 + 2 * tig;
#pragma unroll
            for (int jn = 0; jn < 8; jn++) {
                int n = 8 * jn + gid;
                unsigned vf0 = *(const unsigned*)&V_s[n * AP + kc];
                unsigned vf1 = *(const unsigned*)&V_s[n * AP + kc + 8];
                mma16816h(accO[jn], pa, vf0, vf1);
            }
        }
        __syncthreads();
    }

    const float inv0 = 1.f / li[0], inv1 = 1.f / li[1];
    const int row0 = qrow0 + 16 * wid + gid;
#pragma unroll
    for (int jn = 0; jn < 8; jn++) {
        int col = h * HS + 8 * jn + 2 * tig;
        *(unsigned*)&O_[(size_t)row0 * DIM + col] =
            pkh(__float2half_rn(accO[jn][0] * inv0),
                __float2half_rn(accO[jn][1] * inv0));
        *(unsigned*)&O_[(size_t)(row0 + 8) * DIM + col] =
            pkh(__float2half_rn(accO[jn][2] * inv1),
                __float2half_rn(accO[jn][3] * inv1));
    }
}

// ---------------------------------------------------------------------------
extern "C" void kernel_launch(void* const* d_in, const int* in_sizes, int n_in,
                              void* d_out, int out_size) {
    const float* Xq   = (const float*)d_in[0];
    const float* Xr   = (const float*)d_in[1];
    const float* mask = (const float*)d_in[2];
    const float* Wq   = (const float*)d_in[3];
    const float* Wk   = (const float*)d_in[4];
    const float* Wv   = (const float*)d_in[5];
    const float* Wo   = (const float*)d_in[6];
    float* out = (float*)d_out;

    __half *Xq16, *Xr16, *WqT, *WkT, *WvT, *WoT;
    __half *Q16, *K16, *V16, *Vt16, *O16;
    cudaGetSymbolAddress((void**)&Xq16, g_Xq16); cudaGetSymbolAddress((void**)&Xr16, g_Xr16);
    cudaGetSymbolAddress((void**)&WqT, g_WqT);   cudaGetSymbolAddress((void**)&WkT, g_WkT);
    cudaGetSymbolAddress((void**)&WvT, g_WvT);   cudaGetSymbolAddress((void**)&WoT, g_WoT);
    cudaGetSymbolAddress((void**)&Q16, g_Q16);   cudaGetSymbolAddress((void**)&K16, g_K16);
    cudaGetSymbolAddress((void**)&V16, g_V16);   cudaGetSymbolAddress((void**)&Vt16, g_Vt16);
    cudaGetSymbolAddress((void**)&O16, g_O16);

    cudaFuncSetAttribute(attn_mma, cudaFuncAttributeMaxDynamicSharedMemorySize, ATTN_SMEM);
    cudaFuncSetAttribute(gemm_mma, cudaFuncAttributeMaxDynamicSharedMemorySize, GEMM_SMEM);
    cudaFuncSetAttribute(gemm_kv, cudaFuncAttributeMaxDynamicSharedMemorySize, GEMM_SMEM);

    dim3 gg(DIM / 256, NT_ROWS / 128);          // 128 CTAs = one wave
    dim3 ggkv(DIM / 256, NT_ROWS / 128, 2);     // K and V in one launch

    // launch order puts attn_mma at ncu index 5
    split_x_all<<<dim3(NELEM / 1024, 2), 256>>>(Xq, Xr, Xq16, Xr16);              // 0
    split_wT_all<<<dim3(32, 32, 4), 256>>>(Wq, Wk, Wv, Wo, WqT, WkT, WvT, WoT);   // 1
    gemm_kv<<<ggkv, 512, GEMM_SMEM>>>(Xr16, WkT, WvT, K16, V16);                  // 2
    transpose_v<<<dim3(T_SEQ / 64, NB * NH), 256>>>(V16, Vt16);                   // 3
    gemm_mma<<<gg, 512, GEMM_SMEM>>>(Xq16, WqT, nullptr, Q16, 2, 0.125f);         // 4
    attn_mma<<<dim3(T_SEQ / 128, NH, NB), 256, ATTN_SMEM>>>(
        Q16, K16, Vt16, mask, O16);                                               // 5 <- ncu
    gemm_mma<<<gg, 512, GEMM_SMEM>>>(O16, WoT, out, nullptr, 0, 1.0f);            // 6
}